// round 11
// baseline (speedup 1.0000x reference)
#include <cuda_runtime.h>
#include <cstdint>
#include <cstddef>

// ---------------- problem constants ----------------
#define Bx 2
#define Sx 2048
#define Hx 1024
#define NH 16
#define HD 64
#define BSx (Bx*Sx)          // 4096
#define TOPK 128
#define LN_EPS 1e-5f

typedef unsigned long long u64;

// ---------------- packed f32x2 helpers ----------------
__device__ __forceinline__ u64 pack2(float x, float y) {
    u64 r; asm("mov.b64 %0,{%1,%2};" : "=l"(r) : "f"(x), "f"(y)); return r;
}
__device__ __forceinline__ u64 dup2(float x) { return pack2(x, x); }
__device__ __forceinline__ void unpk2(u64 v, float& x, float& y) {
    asm("mov.b64 {%0,%1},%2;" : "=f"(x), "=f"(y) : "l"(v));
}
__device__ __forceinline__ void fma2(u64& d, u64 a, u64 b) {
    asm("fma.rn.f32x2 %0,%1,%2,%0;" : "+l"(d) : "l"(a), "l"(b));
}
__device__ __forceinline__ void mul2(u64& d, u64 a) {
    asm("mul.rn.f32x2 %0,%0,%1;" : "+l"(d) : "l"(a));
}
__device__ __forceinline__ void add2(u64& d, u64 a) {
    asm("add.rn.f32x2 %0,%0,%1;" : "+l"(d) : "l"(a));
}

__device__ __forceinline__ uint32_t smem_u32(const void* p) {
    uint32_t a;
    asm("{ .reg .u64 t; cvta.to.shared.u64 t, %1; cvt.u32.u64 %0, t; }"
        : "=r"(a) : "l"(p));
    return a;
}
__device__ __forceinline__ void cp16(uint32_t dst, const void* src) {
    asm volatile("cp.async.cg.shared.global [%0], [%1], 16;"
                 :: "r"(dst), "l"(src) : "memory");
}

// ---------------- scratch (device globals; no allocation) ----------------
__device__ float    g_Q[BSx*Hx];
__device__ float    g_K[BSx*Hx];
__device__ float    g_V[BSx*Hx];
__device__ float    g_ctx[BSx*Hx];
__device__ float    g_z[32*16*2048];
__device__ unsigned g_thr[32*16];
__device__ float    g_y[BSx*Hx];
__device__ float    g_vw[NH*HD];
__device__ float    g_ow[NH*HD];

__device__ __forceinline__ unsigned f2ord(float f) {
    unsigned u = __float_as_uint(f);
    return (u >> 31) ? ~u : (u | 0x80000000u);
}

// ---------------- SGEMM (NT): 128x64 tile, 3 CTAs/SM, fused via grid z ------
#define BM 128
#define BN 64
#define BK 16

__global__ __launch_bounds__(256, 3) void sgemm_nt(
    const float* __restrict__ A,
    const float* __restrict__ B0, const float* __restrict__ B1,
    const float* __restrict__ B2,
    float* __restrict__ C0, float* __restrict__ C1, float* __restrict__ C2,
    int M, int N, int K) {
    __shared__ float As[BK][BM + 4];   // k-major
    __shared__ float Bs[BK][BN + 4];   // k-major
    const int tid = threadIdx.x;
    const int tx = tid & 15, ty = tid >> 4;
    const int n0 = blockIdx.x * BN, m0 = blockIdx.y * BM;

    const float* B = (blockIdx.z == 0) ? B0 : (blockIdx.z == 1) ? B1 : B2;
    float*       C = (blockIdx.z == 0) ? C0 : (blockIdx.z == 1) ? C1 : C2;

    u64 acc[8][2];
#pragma unroll
    for (int i = 0; i < 8; i++) { acc[i][0] = 0ull; acc[i][1] = 0ull; }

    const int rA = tid >> 2, cA = (tid & 3) * 4;
    const int rB = tid >> 2, cB = (tid & 3) * 4;

    float4 pa0 = *(const float4*)(A + (size_t)(m0 + rA) * K + cA);
    float4 pa1 = *(const float4*)(A + (size_t)(m0 + rA + 64) * K + cA);
    float4 pb  = *(const float4*)(B + (size_t)(n0 + rB) * K + cB);

    const int nk = K / BK;
    for (int t = 0; t < nk; t++) {
        As[cA + 0][rA] = pa0.x; As[cA + 1][rA] = pa0.y;
        As[cA + 2][rA] = pa0.z; As[cA + 3][rA] = pa0.w;
        As[cA + 0][rA + 64] = pa1.x; As[cA + 1][rA + 64] = pa1.y;
        As[cA + 2][rA + 64] = pa1.z; As[cA + 3][rA + 64] = pa1.w;
        Bs[cB + 0][rB] = pb.x; Bs[cB + 1][rB] = pb.y;
        Bs[cB + 2][rB] = pb.z; Bs[cB + 3][rB] = pb.w;
        __syncthreads();
        if (t + 1 < nk) {
            int k0 = (t + 1) * BK;
            pa0 = *(const float4*)(A + (size_t)(m0 + rA) * K + k0 + cA);
            pa1 = *(const float4*)(A + (size_t)(m0 + rA + 64) * K + k0 + cA);
            pb  = *(const float4*)(B + (size_t)(n0 + rB) * K + k0 + cB);
        }
#pragma unroll
        for (int kk = 0; kk < BK; kk++) {
            float4 a0 = *(const float4*)&As[kk][ty * 8];
            float4 a1 = *(const float4*)&As[kk][ty * 8 + 4];
            ulonglong2 b = *(const ulonglong2*)&Bs[kk][tx * 4];
            u64 ad;
            ad = dup2(a0.x); fma2(acc[0][0], ad, b.x); fma2(acc[0][1], ad, b.y);
            ad = dup2(a0.y); fma2(acc[1][0], ad, b.x); fma2(acc[1][1], ad, b.y);
            ad = dup2(a0.z); fma2(acc[2][0], ad, b.x); fma2(acc[2][1], ad, b.y);
            ad = dup2(a0.w); fma2(acc[3][0], ad, b.x); fma2(acc[3][1], ad, b.y);
            ad = dup2(a1.x); fma2(acc[4][0], ad, b.x); fma2(acc[4][1], ad, b.y);
            ad = dup2(a1.y); fma2(acc[5][0], ad, b.x); fma2(acc[5][1], ad, b.y);
            ad = dup2(a1.z); fma2(acc[6][0], ad, b.x); fma2(acc[6][1], ad, b.y);
            ad = dup2(a1.w); fma2(acc[7][0], ad, b.x); fma2(acc[7][1], ad, b.y);
        }
        __syncthreads();
    }
#pragma unroll
    for (int i = 0; i < 8; i++) {
        size_t off = (size_t)(m0 + ty * 8 + i) * N + n0 + tx * 4;
        ulonglong2 s = {acc[i][0], acc[i][1]};
        *(ulonglong2*)(C + off) = s;
    }
}

// ---------------- per-head LayerNorm on Q and K (in place) ------------------
__global__ __launch_bounds__(256) void ln_kernel(float* __restrict__ Q,
                                                 float* __restrict__ Kp,
                                                 const float* __restrict__ qw,
                                                 const float* __restrict__ qb,
                                                 const float* __restrict__ kw,
                                                 const float* __restrict__ kb) {
    int warp = threadIdx.x >> 5, lane = threadIdx.x & 31;
    int rid = blockIdx.x * 8 + warp;
    float* base;
    const float *w, *bb;
    if (rid < BSx * NH) { base = Q + (size_t)rid * 64; w = qw; bb = qb; }
    else { base = Kp + (size_t)(rid - BSx * NH) * 64; w = kw; bb = kb; }
    float x0 = base[lane], x1 = base[lane + 32];
    float sum = x0 + x1;
#pragma unroll
    for (int off = 16; off; off >>= 1) sum += __shfl_xor_sync(~0u, sum, off);
    float mu = sum * (1.f / 64.f);
    float d0 = x0 - mu, d1 = x1 - mu;
    float vs = d0 * d0 + d1 * d1;
#pragma unroll
    for (int off = 16; off; off >>= 1) vs += __shfl_xor_sync(~0u, vs, off);
    float rs = rsqrtf(vs * (1.f / 64.f) + LN_EPS);
    base[lane]      = d0 * rs * w[lane]      + bb[lane];
    base[lane + 32] = d1 * rs * w[lane + 32] + bb[lane + 32];
}

// ---------------- flash attention v6: pipelined K/V loads -------------------
// QT=128, KT=32, 64 tiles. V triple-buffered via cp.async; K prefetched to
// registers one tile ahead (transpose store to smem). No-max softmax.
// 2 syncs/tile; every buffer reuse is fenced by one of them (audited).
#define QT 128
#define KT 32
#define QS_ST 132
#define KS_ST 38
#define VS_ST 68
#define PS_ST 132
#define OFF_KS 8448                    // 64*132
#define OFF_VS (OFF_KS + 64*KS_ST)     // + 2432
#define VSLOT  (KT*VS_ST)              // 2176 floats per V slot
#define OFF_PS (OFF_VS + 3*VSLOT)      // + 6528
#define ATTN_SMEM ((OFF_PS + KT*PS_ST) * 4)   // 86528 B

__global__ __launch_bounds__(256, 2) void attn_kernel(const float* __restrict__ Qg,
                                                      const float* __restrict__ Kg,
                                                      const float* __restrict__ Vg) {
    extern __shared__ float sm[];
    float* Qs = sm;                 // [k=64][m=128+4]
    float* Ks = sm + OFF_KS;        // [k=64][j=32+6]  (k-major, stride 38)
    float* Vs = sm + OFF_VS;        // 3 x [c=32][d=64+4]
    float* Ps = sm + OFF_PS;        // [c=32][m=128+4]

    const int qt = blockIdx.x, h = blockIdx.y, b = blockIdx.z;
    const int tid = threadIdx.x;
    const int tx = tid & 15, ty = tid >> 4;
    const int q0 = qt * QT;
    const float scale = 0.125f;
    const uint32_t vs_base = smem_u32(sm + OFF_VS);

    const float* qp = Qg + (size_t)(b * Sx + q0) * Hx + h * HD;
#pragma unroll
    for (int it = 0; it < 8; it++) {
        int idx = tid + it * 256;          // 128 rows x 16 float4
        int r = idx >> 4, c4 = (idx & 15) * 4;
        float4 v = *(const float4*)(qp + (size_t)r * Hx + c4);
        Qs[(c4 + 0) * QS_ST + r] = v.x * scale;
        Qs[(c4 + 1) * QS_ST + r] = v.y * scale;
        Qs[(c4 + 2) * QS_ST + r] = v.z * scale;
        Qs[(c4 + 3) * QS_ST + r] = v.w * scale;
    }

    // per-thread K/V load mapping: 32 rows x 16 float4, 2 chunks/thread
    const int lr0 = tid >> 4,        lc0 = (tid & 15) * 4;
    const int lr1 = (tid + 256) >> 4, lc1 = ((tid + 256) & 15) * 4;

    const float* kbase = Kg + (size_t)(b * Sx) * Hx + h * HD;
    const float* vbase = Vg + (size_t)(b * Sx) * Hx + h * HD;

    // prologue: K[0] -> regs; V[0], V[1] -> cp.async slots 0,1
    float4 pk0 = *(const float4*)(kbase + (size_t)lr0 * Hx + lc0);
    float4 pk1 = *(const float4*)(kbase + (size_t)lr1 * Hx + lc1);
#pragma unroll
    for (int sl = 0; sl < 2; sl++) {
        const float* vp = vbase + (size_t)(sl * KT) * Hx;
        cp16(vs_base + (uint32_t)(sl * VSLOT + lr0 * VS_ST + lc0) * 4,
             vp + (size_t)lr0 * Hx + lc0);
        cp16(vs_base + (uint32_t)(sl * VSLOT + lr1 * VS_ST + lc1) * 4,
             vp + (size_t)lr1 * Hx + lc1);
        asm volatile("cp.async.commit_group;" ::: "memory");
    }

    u64 acc2[4][4];
    u64 l2[4];
#pragma unroll
    for (int ip = 0; ip < 4; ip++) {
        l2[ip] = 0ull;
#pragma unroll
        for (int dd = 0; dd < 4; dd++) acc2[ip][dd] = 0ull;
    }

    const int NT = Sx / KT;   // 64
    for (int kt = 0; kt < NT; kt++) {
        // (a) store prefetched K[kt] into Ks (k-major transpose)
        Ks[(lc0 + 0) * KS_ST + lr0] = pk0.x;
        Ks[(lc0 + 1) * KS_ST + lr0] = pk0.y;
        Ks[(lc0 + 2) * KS_ST + lr0] = pk0.z;
        Ks[(lc0 + 3) * KS_ST + lr0] = pk0.w;
        Ks[(lc1 + 0) * KS_ST + lr1] = pk1.x;
        Ks[(lc1 + 1) * KS_ST + lr1] = pk1.y;
        Ks[(lc1 + 2) * KS_ST + lr1] = pk1.z;
        Ks[(lc1 + 3) * KS_ST + lr1] = pk1.w;
        // (b) prefetch K[kt+1] -> regs
        if (kt + 1 < NT) {
            const float* kp = kbase + (size_t)((kt + 1) * KT) * Hx;
            pk0 = *(const float4*)(kp + (size_t)lr0 * Hx + lc0);
            pk1 = *(const float4*)(kp + (size_t)lr1 * Hx + lc1);
        }
        // (c)
        __syncthreads();

        // (d) GEMM1: 8 rows (4 pairs) x 2 cols
        u64 s2[4][2];
#pragma unroll
        for (int ip = 0; ip < 4; ip++) { s2[ip][0] = 0ull; s2[ip][1] = 0ull; }
#pragma unroll 16
        for (int kk = 0; kk < 64; kk++) {
            ulonglong2 q01 = *(const ulonglong2*)&Qs[kk * QS_ST + ty * 8];
            ulonglong2 q23 = *(const ulonglong2*)&Qs[kk * QS_ST + ty * 8 + 4];
            float2 k2 = *(const float2*)&Ks[kk * KS_ST + tx * 2];
            u64 kd;
            kd = dup2(k2.x);
            fma2(s2[0][0], q01.x, kd); fma2(s2[1][0], q01.y, kd);
            fma2(s2[2][0], q23.x, kd); fma2(s2[3][0], q23.y, kd);
            kd = dup2(k2.y);
            fma2(s2[0][1], q01.x, kd); fma2(s2[1][1], q01.y, kd);
            fma2(s2[2][1], q23.x, kd); fma2(s2[3][1], q23.y, kd);
        }

        // (e) p = exp(s); Ps stores; prefetch V[kt+2]
#pragma unroll
        for (int ip = 0; ip < 4; ip++) {
#pragma unroll
            for (int j = 0; j < 2; j++) {
                float f0, f1;
                unpk2(s2[ip][j], f0, f1);
                u64 pr = pack2(__expf(f0), __expf(f1));
                add2(l2[ip], pr);
                *(u64*)&Ps[(tx * 2 + j) * PS_ST + ty * 8 + 2 * ip] = pr;
            }
        }
        if (kt + 2 < NT) {
            int sl = (kt + 2) % 3;
            const float* vp = vbase + (size_t)((kt + 2) * KT) * Hx;
            cp16(vs_base + (uint32_t)(sl * VSLOT + lr0 * VS_ST + lc0) * 4,
                 vp + (size_t)lr0 * Hx + lc0);
            cp16(vs_base + (uint32_t)(sl * VSLOT + lr1 * VS_ST + lc1) * 4,
                 vp + (size_t)lr1 * Hx + lc1);
        }
        asm volatile("cp.async.commit_group;" ::: "memory");
        // (f) V[kt] ready when at most 2 newer groups pending
        asm volatile("cp.async.wait_group 2;" ::: "memory");
        // (g)
        __syncthreads();

        // (h) GEMM2 on V slot kt%3
        const float* Vt = Vs + (kt % 3) * VSLOT;
#pragma unroll 8
        for (int c = 0; c < KT; c++) {
            ulonglong2 pA = *(const ulonglong2*)&Ps[c * PS_ST + ty * 8];
            ulonglong2 pB = *(const ulonglong2*)&Ps[c * PS_ST + ty * 8 + 4];
            float4 vv = *(const float4*)&Vt[c * VS_ST + tx * 4];
            u64 vd;
            vd = dup2(vv.x);
            fma2(acc2[0][0], pA.x, vd); fma2(acc2[1][0], pA.y, vd);
            fma2(acc2[2][0], pB.x, vd); fma2(acc2[3][0], pB.y, vd);
            vd = dup2(vv.y);
            fma2(acc2[0][1], pA.x, vd); fma2(acc2[1][1], pA.y, vd);
            fma2(acc2[2][1], pB.x, vd); fma2(acc2[3][1], pB.y, vd);
            vd = dup2(vv.z);
            fma2(acc2[0][2], pA.x, vd); fma2(acc2[1][2], pA.y, vd);
            fma2(acc2[2][2], pB.x, vd); fma2(acc2[3][2], pB.y, vd);
            vd = dup2(vv.w);
            fma2(acc2[0][3], pA.x, vd); fma2(acc2[1][3], pA.y, vd);
            fma2(acc2[2][3], pB.x, vd); fma2(acc2[3][3], pB.y, vd);
        }
    }

    // one-time paired row-sum reduction across the 16-lane tx group
#pragma unroll
    for (int ip = 0; ip < 4; ip++) {
#pragma unroll
        for (int off = 8; off; off >>= 1) {
            u64 o = __shfl_xor_sync(~0u, l2[ip], off, 16);
            add2(l2[ip], o);
        }
    }

    float* ob = g_ctx + ((size_t)(b * NH + h) * Sx + q0) * HD;
#pragma unroll
    for (int ip = 0; ip < 4; ip++) {
        float la, lb;
        unpk2(l2[ip], la, lb);
        float ia = 1.f / la, ib = 1.f / lb;
        float4 r0, r1;
        float x, y;
        unpk2(acc2[ip][0], x, y); r0.x = x * ia; r1.x = y * ib;
        unpk2(acc2[ip][1], x, y); r0.y = x * ia; r1.y = y * ib;
        unpk2(acc2[ip][2], x, y); r0.z = x * ia; r1.z = y * ib;
        unpk2(acc2[ip][3], x, y); r0.w = x * ia; r1.w = y * ib;
        *(float4*)(ob + (size_t)(ty * 8 + 2 * ip) * HD + tx * 4)     = r0;
        *(float4*)(ob + (size_t)(ty * 8 + 2 * ip + 1) * HD + tx * 4) = r1;
    }
}

// ---------------- z = mixed-context . vw  ------------------------------------
__global__ __launch_bounds__(256) void z_kernel() {
    __shared__ float cs[128][65];
    __shared__ float vws[NH * HD];
    int t = threadIdx.x;
    int n = blockIdx.y, m0 = blockIdx.x * 128;
    for (int i = t; i < NH * HD; i += 256) vws[i] = g_vw[i];
    int b = n >> 4, hi = n & 15;
#pragma unroll 8
    for (int it = 0; it < 32; it++) {
        int f = t + it * 256;
        int j = f >> 6, d = f & 63;
        int m = m0 + j;
        int t2 = hi * Sx + m;
        int s = t2 >> 4, hh = t2 & 15;
        cs[j][d] = g_ctx[((size_t)(b * NH + hh) * Sx + s) * HD + d];
    }
    __syncthreads();
#pragma unroll 1
    for (int p = 0; p < 8; p++) {
        int h2 = p * 2 + (t >> 7);
        int ml = t & 127;
        const float* vr = &vws[h2 * HD];
        float a = 0.f;
#pragma unroll
        for (int d = 0; d < 64; d++) a += cs[ml][d] * vr[d];
        g_z[((size_t)n * 16 + h2) * Sx + m0 + ml] = a;
    }
}

// ---------------- top-128 threshold per row ----------------------------------
__global__ __launch_bounds__(256) void topk_kernel() {
    int row = blockIdx.x, t = threadIdx.x;
    const float* zr = g_z + (size_t)row * Sx;
    unsigned v[8];
#pragma unroll
    for (int i = 0; i < 8; i++) v[i] = f2ord(zr[t + i * 256]);
    __shared__ int scnt;
    unsigned lo = 0u, hi = 0xFFFFFFFFu;
    while (lo < hi) {
        unsigned mid = lo + ((hi - lo) >> 1);
        int c = 0;
#pragma unroll
        for (int i = 0; i < 8; i++) c += (v[i] > mid);
#pragma unroll
        for (int off = 16; off; off >>= 1) c += __shfl_xor_sync(~0u, c, off);
        __syncthreads();
        if (t == 0) scnt = 0;
        __syncthreads();
        if ((t & 31) == 0) atomicAdd(&scnt, c);
        __syncthreads();
        int tot = scnt;
        if (tot >= TOPK) lo = mid + 1; else hi = mid;
    }
    if (t == 0) g_thr[row] = lo;
}

// ---------------- y = sparse(z) . ow -----------------------------------------
__global__ __launch_bounds__(256) void y_kernel() {
    __shared__ float zs[16][17];
    __shared__ float ows[NH * HD];
    int t = threadIdx.x;
    int s = blockIdx.x, b = blockIdx.y;
    for (int i = t; i < NH * HD; i += 256) ows[i] = g_ow[i];
    {
        int h = t >> 4, h2 = t & 15;
        int n = b * 16 + h;
        float zv = g_z[((size_t)n * 16 + h2) * Sx + s];
        zs[h][h2] = (f2ord(zv) >= g_thr[n * 16 + h2]) ? zv : 0.f;
    }
    __syncthreads();
#pragma unroll
    for (int k2 = 0; k2 < 4; k2++) {
        int dg = t + k2 * 256;
        int h = dg >> 6, d = dg & 63;
        float a = 0.f;
#pragma unroll
        for (int h2 = 0; h2 < 16; h2++) a += zs[h][h2] * ows[h2 * HD + d];
        g_y[((size_t)(b * Sx + s)) * Hx + dg] = a;
    }
}

// ---------------- reduce sparse weight means (parallelized) ------------------
__global__ void prep_kernel(const float* __restrict__ swv,
                            const float* __restrict__ swo) {
    int t = blockIdx.x * 64 + threadIdx.x;
    int h = t >> 6, d = t & 63;
    float s1 = 0.f, s2 = 0.f;
#pragma unroll 4
    for (int k = 0; k < 128; k++) {
        s1 += swv[((size_t)(h * 64 + d)) * 128 + k];
        s2 += swo[((size_t)(h * 128 + k)) * 64 + d];
    }
    g_vw[t] = s1 * (1.f / 128.f);
    g_ow[t] = s2 * (1.f / 128.f);
}

// ---------------- launch ----------------------------------------------------
extern "C" void kernel_launch(void* const* d_in, const int* in_sizes, int n_in,
                              void* d_out, int out_size) {
    const float* x   = (const float*)d_in[0];
    const float* WQ  = (const float*)d_in[1];
    const float* WK  = (const float*)d_in[2];
    const float* WV  = (const float*)d_in[3];
    const float* WO  = (const float*)d_in[4];
    const float* qw  = (const float*)d_in[5];
    const float* qb  = (const float*)d_in[6];
    const float* kw  = (const float*)d_in[7];
    const float* kb  = (const float*)d_in[8];
    const float* swv = (const float*)d_in[9];
    const float* swo = (const float*)d_in[10];
    float* out = (float*)d_out;

    float *pQ, *pK, *pV, *pY;
    cudaGetSymbolAddress((void**)&pQ, g_Q);
    cudaGetSymbolAddress((void**)&pK, g_K);
    cudaGetSymbolAddress((void**)&pV, g_V);
    cudaGetSymbolAddress((void**)&pY, g_y);

    cudaFuncSetAttribute(attn_kernel,
                         cudaFuncAttributeMaxDynamicSharedMemorySize, ATTN_SMEM);

    prep_kernel<<<16, 64>>>(swv, swo);

    sgemm_nt<<<dim3(Hx / BN, BSx / BM, 3), 256>>>(
        x, WQ, WK, WV, pQ, pK, pV, BSx, Hx, Hx);

    ln_kernel<<<16384, 256>>>(pQ, pK, qw, qb, kw, kb);

    attn_kernel<<<dim3(Sx / QT, NH, Bx), 256, ATTN_SMEM>>>(pQ, pK, pV);

    z_kernel<<<dim3(Sx / 128, 32), 256>>>();
    topk_kernel<<<512, 256>>>();
    y_kernel<<<dim3(Sx, Bx), 256>>>();

    sgemm_nt<<<dim3(Hx / BN, BSx / BM, 1), 256>>>(
        pY, WO, WO, WO, out, out, out, BSx, Hx, Hx);
}

// round 12
// speedup vs baseline: 1.0174x; 1.0174x over previous
#include <cuda_runtime.h>
#include <cstdint>
#include <cstddef>

// ---------------- problem constants ----------------
#define Bx 2
#define Sx 2048
#define Hx 1024
#define NH 16
#define HD 64
#define BSx (Bx*Sx)          // 4096
#define TOPK 128
#define LN_EPS 1e-5f

typedef unsigned long long u64;

// ---------------- packed f32x2 helpers ----------------
__device__ __forceinline__ u64 pack2(float x, float y) {
    u64 r; asm("mov.b64 %0,{%1,%2};" : "=l"(r) : "f"(x), "f"(y)); return r;
}
__device__ __forceinline__ u64 dup2(float x) { return pack2(x, x); }
__device__ __forceinline__ void unpk2(u64 v, float& x, float& y) {
    asm("mov.b64 {%0,%1},%2;" : "=f"(x), "=f"(y) : "l"(v));
}
__device__ __forceinline__ void fma2(u64& d, u64 a, u64 b) {
    asm("fma.rn.f32x2 %0,%1,%2,%0;" : "+l"(d) : "l"(a), "l"(b));
}
__device__ __forceinline__ void mul2(u64& d, u64 a) {
    asm("mul.rn.f32x2 %0,%0,%1;" : "+l"(d) : "l"(a));
}
__device__ __forceinline__ void add2(u64& d, u64 a) {
    asm("add.rn.f32x2 %0,%0,%1;" : "+l"(d) : "l"(a));
}

// ---------------- scratch (device globals; no allocation) ----------------
__device__ float    g_Q[BSx*Hx];
__device__ float    g_K[BSx*Hx];
__device__ float    g_V[BSx*Hx];
__device__ float    g_ctx[BSx*Hx];
__device__ float    g_z[32*16*2048];
__device__ unsigned g_thr[32*16];
__device__ float    g_y[BSx*Hx];
__device__ float    g_vw[NH*HD];
__device__ float    g_ow[NH*HD];

__device__ __forceinline__ unsigned f2ord(float f) {
    unsigned u = __float_as_uint(f);
    return (u >> 31) ? ~u : (u | 0x80000000u);
}

// ---------------- SGEMM v4 (NT): 128x64, double-buffered, 1 sync/tile -------
// C[M,N] = A[M,K] * B[N,K]^T. 3 CTAs/SM, fused QKV via grid z.
#define BM 128
#define BN 64
#define BK 16

__global__ __launch_bounds__(256, 3) void sgemm_nt(
    const float* __restrict__ A,
    const float* __restrict__ B0, const float* __restrict__ B1,
    const float* __restrict__ B2,
    float* __restrict__ C0, float* __restrict__ C1, float* __restrict__ C2,
    int M, int N, int K) {
    __shared__ float As[2][BK][BM + 4];   // k-major, ping-pong
    __shared__ float Bs[2][BK][BN + 4];
    const int tid = threadIdx.x;
    const int tx = tid & 15, ty = tid >> 4;
    const int n0 = blockIdx.x * BN, m0 = blockIdx.y * BM;

    const float* B = (blockIdx.z == 0) ? B0 : (blockIdx.z == 1) ? B1 : B2;
    float*       C = (blockIdx.z == 0) ? C0 : (blockIdx.z == 1) ? C1 : C2;

    u64 acc[8][2];
#pragma unroll
    for (int i = 0; i < 8; i++) { acc[i][0] = 0ull; acc[i][1] = 0ull; }

    const int rA = tid >> 2, cA = (tid & 3) * 4;
    const int rB = tid >> 2, cB = (tid & 3) * 4;

    float4 pa0 = *(const float4*)(A + (size_t)(m0 + rA) * K + cA);
    float4 pa1 = *(const float4*)(A + (size_t)(m0 + rA + 64) * K + cA);
    float4 pb  = *(const float4*)(B + (size_t)(n0 + rB) * K + cB);

    const int nk = K / BK;
    for (int t = 0; t < nk; t++) {
        const int buf = t & 1;
        As[buf][cA + 0][rA] = pa0.x; As[buf][cA + 1][rA] = pa0.y;
        As[buf][cA + 2][rA] = pa0.z; As[buf][cA + 3][rA] = pa0.w;
        As[buf][cA + 0][rA + 64] = pa1.x; As[buf][cA + 1][rA + 64] = pa1.y;
        As[buf][cA + 2][rA + 64] = pa1.z; As[buf][cA + 3][rA + 64] = pa1.w;
        Bs[buf][cB + 0][rB] = pb.x; Bs[buf][cB + 1][rB] = pb.y;
        Bs[buf][cB + 2][rB] = pb.z; Bs[buf][cB + 3][rB] = pb.w;
        __syncthreads();                    // only sync this tile
        if (t + 1 < nk) {
            int k0 = (t + 1) * BK;
            pa0 = *(const float4*)(A + (size_t)(m0 + rA) * K + k0 + cA);
            pa1 = *(const float4*)(A + (size_t)(m0 + rA + 64) * K + k0 + cA);
            pb  = *(const float4*)(B + (size_t)(n0 + rB) * K + k0 + cB);
        }
#pragma unroll
        for (int kk = 0; kk < BK; kk++) {
            float4 a0 = *(const float4*)&As[buf][kk][ty * 8];
            float4 a1 = *(const float4*)&As[buf][kk][ty * 8 + 4];
            ulonglong2 b = *(const ulonglong2*)&Bs[buf][kk][tx * 4];
            u64 ad;
            ad = dup2(a0.x); fma2(acc[0][0], ad, b.x); fma2(acc[0][1], ad, b.y);
            ad = dup2(a0.y); fma2(acc[1][0], ad, b.x); fma2(acc[1][1], ad, b.y);
            ad = dup2(a0.z); fma2(acc[2][0], ad, b.x); fma2(acc[2][1], ad, b.y);
            ad = dup2(a0.w); fma2(acc[3][0], ad, b.x); fma2(acc[3][1], ad, b.y);
            ad = dup2(a1.x); fma2(acc[4][0], ad, b.x); fma2(acc[4][1], ad, b.y);
            ad = dup2(a1.y); fma2(acc[5][0], ad, b.x); fma2(acc[5][1], ad, b.y);
            ad = dup2(a1.z); fma2(acc[6][0], ad, b.x); fma2(acc[6][1], ad, b.y);
            ad = dup2(a1.w); fma2(acc[7][0], ad, b.x); fma2(acc[7][1], ad, b.y);
        }
        // no trailing sync: next tile writes the OTHER buffer; the sync above
        // (passed by all warps after finishing the prior tile's compute)
        // already fences reuse of that buffer.
    }
#pragma unroll
    for (int i = 0; i < 8; i++) {
        size_t off = (size_t)(m0 + ty * 8 + i) * N + n0 + tx * 4;
        ulonglong2 s = {acc[i][0], acc[i][1]};
        *(ulonglong2*)(C + off) = s;
    }
}

// ---------------- per-head LayerNorm on Q and K (in place) ------------------
__global__ __launch_bounds__(256) void ln_kernel(float* __restrict__ Q,
                                                 float* __restrict__ Kp,
                                                 const float* __restrict__ qw,
                                                 const float* __restrict__ qb,
                                                 const float* __restrict__ kw,
                                                 const float* __restrict__ kb) {
    int warp = threadIdx.x >> 5, lane = threadIdx.x & 31;
    int rid = blockIdx.x * 8 + warp;
    float* base;
    const float *w, *bb;
    if (rid < BSx * NH) { base = Q + (size_t)rid * 64; w = qw; bb = qb; }
    else { base = Kp + (size_t)(rid - BSx * NH) * 64; w = kw; bb = kb; }
    float x0 = base[lane], x1 = base[lane + 32];
    float sum = x0 + x1;
#pragma unroll
    for (int off = 16; off; off >>= 1) sum += __shfl_xor_sync(~0u, sum, off);
    float mu = sum * (1.f / 64.f);
    float d0 = x0 - mu, d1 = x1 - mu;
    float vs = d0 * d0 + d1 * d1;
#pragma unroll
    for (int off = 16; off; off >>= 1) vs += __shfl_xor_sync(~0u, vs, off);
    float rs = rsqrtf(vs * (1.f / 64.f) + LN_EPS);
    base[lane]      = d0 * rs * w[lane]      + bb[lane];
    base[lane + 32] = d1 * rs * w[lane + 32] + bb[lane + 32];
}

// ---------------- flash attention v5 (R10 form): QT=128, KT=64 --------------
// No-max softmax (LN'd rows: |s| <= 8). grid (S/128, nh, B), block 256:
// tx(16) -> cols tx*4..+3; ty(16) -> rows ty*8..+7 as 4 f32x2 row-pairs.
#define QT 128
#define KT 64
#define QS_ST 132
#define KS_ST 68
#define VS_ST 68
#define PS_ST 132
#define OFF_KS (64*QS_ST)
#define OFF_VS (OFF_KS + 64*KS_ST)
#define OFF_PS (OFF_VS + KT*VS_ST)
#define ATTN_SMEM ((OFF_PS + KT*PS_ST) * 4)

__global__ __launch_bounds__(256, 2) void attn_kernel(const float* __restrict__ Qg,
                                                      const float* __restrict__ Kg,
                                                      const float* __restrict__ Vg) {
    extern __shared__ float sm[];
    float* Qs = sm;              // [k=64][m=128+4]
    float* Ks = sm + OFF_KS;     // [k=64][j=64+4]
    float* Vs = sm + OFF_VS;     // [c=64][d=64+4]
    float* Ps = sm + OFF_PS;     // [c=64][m=128+4]

    const int qt = blockIdx.x, h = blockIdx.y, b = blockIdx.z;
    const int tid = threadIdx.x;
    const int tx = tid & 15, ty = tid >> 4;
    const int q0 = qt * QT;
    const float scale = 0.125f;

    const float* qp = Qg + (size_t)(b * Sx + q0) * Hx + h * HD;
#pragma unroll
    for (int it = 0; it < 8; it++) {
        int idx = tid + it * 256;          // 128 rows x 16 float4
        int r = idx >> 4, c4 = (idx & 15) * 4;
        float4 v = *(const float4*)(qp + (size_t)r * Hx + c4);
        Qs[(c4 + 0) * QS_ST + r] = v.x * scale;
        Qs[(c4 + 1) * QS_ST + r] = v.y * scale;
        Qs[(c4 + 2) * QS_ST + r] = v.z * scale;
        Qs[(c4 + 3) * QS_ST + r] = v.w * scale;
    }

    u64 acc2[4][4];   // [row-pair ip][ctx col dd]
    u64 l2[4];
#pragma unroll
    for (int ip = 0; ip < 4; ip++) {
        l2[ip] = 0ull;
#pragma unroll
        for (int dd = 0; dd < 4; dd++) acc2[ip][dd] = 0ull;
    }

    for (int kt = 0; kt < Sx / KT; kt++) {
        __syncthreads();    // protect Ks/Vs/Ps against overwrite
        const float* kp = Kg + (size_t)(b * Sx + kt * KT) * Hx + h * HD;
        const float* vp = Vg + (size_t)(b * Sx + kt * KT) * Hx + h * HD;
#pragma unroll
        for (int it = 0; it < 4; it++) {
            int idx = tid + it * 256;      // 64 rows x 16 float4
            int r = idx >> 4, c4 = (idx & 15) * 4;
            float4 kv = *(const float4*)(kp + (size_t)r * Hx + c4);
            Ks[(c4 + 0) * KS_ST + r] = kv.x;
            Ks[(c4 + 1) * KS_ST + r] = kv.y;
            Ks[(c4 + 2) * KS_ST + r] = kv.z;
            Ks[(c4 + 3) * KS_ST + r] = kv.w;
            float4 vv = *(const float4*)(vp + (size_t)r * Hx + c4);
            *(float4*)&Vs[r * VS_ST + c4] = vv;
        }
        __syncthreads();

        // GEMM1: 8 rows (4 f32x2 pairs) x 4 cols per thread
        u64 s2[4][4];
#pragma unroll
        for (int ip = 0; ip < 4; ip++)
#pragma unroll
            for (int j = 0; j < 4; j++) s2[ip][j] = 0ull;
#pragma unroll 16
        for (int kk = 0; kk < 64; kk++) {
            ulonglong2 q01 = *(const ulonglong2*)&Qs[kk * QS_ST + ty * 8];
            ulonglong2 q23 = *(const ulonglong2*)&Qs[kk * QS_ST + ty * 8 + 4];
            float4 k4 = *(const float4*)&Ks[kk * KS_ST + tx * 4];
            u64 kd;
            kd = dup2(k4.x);
            fma2(s2[0][0], q01.x, kd); fma2(s2[1][0], q01.y, kd);
            fma2(s2[2][0], q23.x, kd); fma2(s2[3][0], q23.y, kd);
            kd = dup2(k4.y);
            fma2(s2[0][1], q01.x, kd); fma2(s2[1][1], q01.y, kd);
            fma2(s2[2][1], q23.x, kd); fma2(s2[3][1], q23.y, kd);
            kd = dup2(k4.z);
            fma2(s2[0][2], q01.x, kd); fma2(s2[1][2], q01.y, kd);
            fma2(s2[2][2], q23.x, kd); fma2(s2[3][2], q23.y, kd);
            kd = dup2(k4.w);
            fma2(s2[0][3], q01.x, kd); fma2(s2[1][3], q01.y, kd);
            fma2(s2[2][3], q23.x, kd); fma2(s2[3][3], q23.y, kd);
        }

        // p = exp(s); local l accumulation; row-pair u64 stores into Ps[c][m]
#pragma unroll
        for (int ip = 0; ip < 4; ip++) {
#pragma unroll
            for (int j = 0; j < 4; j++) {
                float f0, f1;
                unpk2(s2[ip][j], f0, f1);
                u64 pr = pack2(__expf(f0), __expf(f1));
                add2(l2[ip], pr);
                *(u64*)&Ps[(tx * 4 + j) * PS_ST + ty * 8 + 2 * ip] = pr;
            }
        }
        __syncthreads();

        // GEMM2: acc2[ip][dd] += P(row-pair, c) * V[c][tx*4+dd]
#pragma unroll 8
        for (int c = 0; c < KT; c++) {
            ulonglong2 pA = *(const ulonglong2*)&Ps[c * PS_ST + ty * 8];
            ulonglong2 pB = *(const ulonglong2*)&Ps[c * PS_ST + ty * 8 + 4];
            float4 vv = *(const float4*)&Vs[c * VS_ST + tx * 4];
            u64 vd;
            vd = dup2(vv.x);
            fma2(acc2[0][0], pA.x, vd); fma2(acc2[1][0], pA.y, vd);
            fma2(acc2[2][0], pB.x, vd); fma2(acc2[3][0], pB.y, vd);
            vd = dup2(vv.y);
            fma2(acc2[0][1], pA.x, vd); fma2(acc2[1][1], pA.y, vd);
            fma2(acc2[2][1], pB.x, vd); fma2(acc2[3][1], pB.y, vd);
            vd = dup2(vv.z);
            fma2(acc2[0][2], pA.x, vd); fma2(acc2[1][2], pA.y, vd);
            fma2(acc2[2][2], pB.x, vd); fma2(acc2[3][2], pB.y, vd);
            vd = dup2(vv.w);
            fma2(acc2[0][3], pA.x, vd); fma2(acc2[1][3], pA.y, vd);
            fma2(acc2[2][3], pB.x, vd); fma2(acc2[3][3], pB.y, vd);
        }
    }

    // one-time paired row-sum reduction across the 16-lane tx group
#pragma unroll
    for (int ip = 0; ip < 4; ip++) {
#pragma unroll
        for (int off = 8; off; off >>= 1) {
            u64 o = __shfl_xor_sync(~0u, l2[ip], off, 16);
            add2(l2[ip], o);
        }
    }

    float* ob = g_ctx + ((size_t)(b * NH + h) * Sx + q0) * HD;
#pragma unroll
    for (int ip = 0; ip < 4; ip++) {
        float la, lb;
        unpk2(l2[ip], la, lb);
        float ia = 1.f / la, ib = 1.f / lb;
        float4 r0, r1;
        float x, y;
        unpk2(acc2[ip][0], x, y); r0.x = x * ia; r1.x = y * ib;
        unpk2(acc2[ip][1], x, y); r0.y = x * ia; r1.y = y * ib;
        unpk2(acc2[ip][2], x, y); r0.z = x * ia; r1.z = y * ib;
        unpk2(acc2[ip][3], x, y); r0.w = x * ia; r1.w = y * ib;
        *(float4*)(ob + (size_t)(ty * 8 + 2 * ip) * HD + tx * 4)     = r0;
        *(float4*)(ob + (size_t)(ty * 8 + 2 * ip + 1) * HD + tx * 4) = r1;
    }
}

// ---------------- z = mixed-context . vw  ------------------------------------
__global__ __launch_bounds__(256) void z_kernel() {
    __shared__ float cs[128][65];
    __shared__ float vws[NH * HD];
    int t = threadIdx.x;
    int n = blockIdx.y, m0 = blockIdx.x * 128;
    for (int i = t; i < NH * HD; i += 256) vws[i] = g_vw[i];
    int b = n >> 4, hi = n & 15;
#pragma unroll 8
    for (int it = 0; it < 32; it++) {
        int f = t + it * 256;
        int j = f >> 6, d = f & 63;
        int m = m0 + j;
        int t2 = hi * Sx + m;
        int s = t2 >> 4, hh = t2 & 15;
        cs[j][d] = g_ctx[((size_t)(b * NH + hh) * Sx + s) * HD + d];
    }
    __syncthreads();
#pragma unroll 1
    for (int p = 0; p < 8; p++) {
        int h2 = p * 2 + (t >> 7);
        int ml = t & 127;
        const float* vr = &vws[h2 * HD];
        float a = 0.f;
#pragma unroll
        for (int d = 0; d < 64; d++) a += cs[ml][d] * vr[d];
        g_z[((size_t)n * 16 + h2) * Sx + m0 + ml] = a;
    }
}

// ---------------- top-128 threshold per row ----------------------------------
__global__ __launch_bounds__(256) void topk_kernel() {
    int row = blockIdx.x, t = threadIdx.x;
    const float* zr = g_z + (size_t)row * Sx;
    unsigned v[8];
#pragma unroll
    for (int i = 0; i < 8; i++) v[i] = f2ord(zr[t + i * 256]);
    __shared__ int scnt;
    unsigned lo = 0u, hi = 0xFFFFFFFFu;
    while (lo < hi) {
        unsigned mid = lo + ((hi - lo) >> 1);
        int c = 0;
#pragma unroll
        for (int i = 0; i < 8; i++) c += (v[i] > mid);
#pragma unroll
        for (int off = 16; off; off >>= 1) c += __shfl_xor_sync(~0u, c, off);
        __syncthreads();
        if (t == 0) scnt = 0;
        __syncthreads();
        if ((t & 31) == 0) atomicAdd(&scnt, c);
        __syncthreads();
        int tot = scnt;
        if (tot >= TOPK) lo = mid + 1; else hi = mid;
    }
    if (t == 0) g_thr[row] = lo;
}

// ---------------- y = sparse(z) . ow -----------------------------------------
__global__ __launch_bounds__(256) void y_kernel() {
    __shared__ float zs[16][17];
    __shared__ float ows[NH * HD];
    int t = threadIdx.x;
    int s = blockIdx.x, b = blockIdx.y;
    for (int i = t; i < NH * HD; i += 256) ows[i] = g_ow[i];
    {
        int h = t >> 4, h2 = t & 15;
        int n = b * 16 + h;
        float zv = g_z[((size_t)n * 16 + h2) * Sx + s];
        zs[h][h2] = (f2ord(zv) >= g_thr[n * 16 + h2]) ? zv : 0.f;
    }
    __syncthreads();
#pragma unroll
    for (int k2 = 0; k2 < 4; k2++) {
        int dg = t + k2 * 256;
        int h = dg >> 6, d = dg & 63;
        float a = 0.f;
#pragma unroll
        for (int h2 = 0; h2 < 16; h2++) a += zs[h][h2] * ows[h2 * HD + d];
        g_y[((size_t)(b * Sx + s)) * Hx + dg] = a;
    }
}

// ---------------- reduce sparse weight means (parallelized) ------------------
__global__ void prep_kernel(const float* __restrict__ swv,
                            const float* __restrict__ swo) {
    int t = blockIdx.x * 64 + threadIdx.x;
    int h = t >> 6, d = t & 63;
    float s1 = 0.f, s2 = 0.f;
#pragma unroll 4
    for (int k = 0; k < 128; k++) {
        s1 += swv[((size_t)(h * 64 + d)) * 128 + k];
        s2 += swo[((size_t)(h * 128 + k)) * 64 + d];
    }
    g_vw[t] = s1 * (1.f / 128.f);
    g_ow[t] = s2 * (1.f / 128.f);
}

// ---------------- launch ----------------------------------------------------
extern "C" void kernel_launch(void* const* d_in, const int* in_sizes, int n_in,
                              void* d_out, int out_size) {
    const float* x   = (const float*)d_in[0];
    const float* WQ  = (const float*)d_in[1];
    const float* WK  = (const float*)d_in[2];
    const float* WV  = (const float*)d_in[3];
    const float* WO  = (const float*)d_in[4];
    const float* qw  = (const float*)d_in[5];
    const float* qb  = (const float*)d_in[6];
    const float* kw  = (const float*)d_in[7];
    const float* kb  = (const float*)d_in[8];
    const float* swv = (const float*)d_in[9];
    const float* swo = (const float*)d_in[10];
    float* out = (float*)d_out;

    float *pQ, *pK, *pV, *pY;
    cudaGetSymbolAddress((void**)&pQ, g_Q);
    cudaGetSymbolAddress((void**)&pK, g_K);
    cudaGetSymbolAddress((void**)&pV, g_V);
    cudaGetSymbolAddress((void**)&pY, g_y);

    cudaFuncSetAttribute(attn_kernel,
                         cudaFuncAttributeMaxDynamicSharedMemorySize, ATTN_SMEM);

    prep_kernel<<<16, 64>>>(swv, swo);

    sgemm_nt<<<dim3(Hx / BN, BSx / BM, 3), 256>>>(
        x, WQ, WK, WV, pQ, pK, pV, BSx, Hx, Hx);

    ln_kernel<<<16384, 256>>>(pQ, pK, qw, qb, kw, kb);

    attn_kernel<<<dim3(Sx / QT, NH, Bx), 256, ATTN_SMEM>>>(pQ, pK, pV);

    z_kernel<<<dim3(Sx / 128, 32), 256>>>();
    topk_kernel<<<512, 256>>>();
    y_kernel<<<dim3(Sx, Bx), 256>>>();

    sgemm_nt<<<dim3(Hx / BN, BSx / BM, 1), 256>>>(
        pY, WO, WO, WO, out, out, out, BSx, Hx, Hx);
}

// round 13
// speedup vs baseline: 1.1168x; 1.0977x over previous
#include <cuda_runtime.h>
#include <cstdint>
#include <cstddef>

// ---------------- problem constants ----------------
#define Bx 2
#define Sx 2048
#define Hx 1024
#define NH 16
#define HD 64
#define BSx (Bx*Sx)          // 4096
#define TOPK 128
#define LN_EPS 1e-5f

typedef unsigned long long u64;

// ---------------- packed f32x2 helpers ----------------
__device__ __forceinline__ u64 pack2(float x, float y) {
    u64 r; asm("mov.b64 %0,{%1,%2};" : "=l"(r) : "f"(x), "f"(y)); return r;
}
__device__ __forceinline__ u64 dup2(float x) { return pack2(x, x); }
__device__ __forceinline__ void unpk2(u64 v, float& x, float& y) {
    asm("mov.b64 {%0,%1},%2;" : "=f"(x), "=f"(y) : "l"(v));
}
__device__ __forceinline__ void fma2(u64& d, u64 a, u64 b) {
    asm("fma.rn.f32x2 %0,%1,%2,%0;" : "+l"(d) : "l"(a), "l"(b));
}
__device__ __forceinline__ void mul2(u64& d, u64 a) {
    asm("mul.rn.f32x2 %0,%0,%1;" : "+l"(d) : "l"(a));
}
__device__ __forceinline__ void add2(u64& d, u64 a) {
    asm("add.rn.f32x2 %0,%0,%1;" : "+l"(d) : "l"(a));
}

// ---------------- scratch (device globals; no allocation) ----------------
__device__ float    g_Q[BSx*Hx];
__device__ float    g_K[BSx*Hx];
__device__ float    g_V[BSx*Hx];
__device__ float    g_ctx[BSx*Hx];
__device__ float    g_z[32*16*2048];
__device__ unsigned g_thr[32*16];
__device__ float    g_vw[NH*HD];
__device__ float    g_ow[NH*HD];
__device__ float    g_W2[Hx*256];      // W2[o][h*16+h2] = sum_d ow[h2,d]*WO[o, h*64+d]

__device__ __forceinline__ unsigned f2ord(float f) {
    unsigned u = __float_as_uint(f);
    return (u >> 31) ? ~u : (u | 0x80000000u);
}

// ---------------- SGEMM (NT) + fused per-head LayerNorm epilogue ------------
// C[M,N] = A[M,K] * B[N,K]^T. 128x64 tile, double-buffered, 3 CTAs/SM.
// blockIdx.z: 0=Q (LN qw/qb), 1=K (LN kw/kb), 2=V (no LN). BN=64 == head dim,
// n0 % 64 == 0, so each output row chunk is a full head -> LN reduces over the
// 16-lane tx group.
#define BM 128
#define BN 64
#define BK 16

__global__ __launch_bounds__(256, 3) void sgemm_qkv(
    const float* __restrict__ A,
    const float* __restrict__ B0, const float* __restrict__ B1,
    const float* __restrict__ B2,
    float* __restrict__ C0, float* __restrict__ C1, float* __restrict__ C2,
    const float* __restrict__ qw, const float* __restrict__ qb,
    const float* __restrict__ kw, const float* __restrict__ kb,
    int M, int N, int K) {
    __shared__ float As[2][BK][BM + 4];   // k-major ping-pong
    __shared__ float Bs[2][BK][BN + 4];
    const int tid = threadIdx.x;
    const int tx = tid & 15, ty = tid >> 4;
    const int n0 = blockIdx.x * BN, m0 = blockIdx.y * BM;

    const float* B = (blockIdx.z == 0) ? B0 : (blockIdx.z == 1) ? B1 : B2;
    float*       C = (blockIdx.z == 0) ? C0 : (blockIdx.z == 1) ? C1 : C2;

    u64 acc[8][2];
#pragma unroll
    for (int i = 0; i < 8; i++) { acc[i][0] = 0ull; acc[i][1] = 0ull; }

    const int rA = tid >> 2, cA = (tid & 3) * 4;
    const int rB = tid >> 2, cB = (tid & 3) * 4;

    float4 pa0 = *(const float4*)(A + (size_t)(m0 + rA) * K + cA);
    float4 pa1 = *(const float4*)(A + (size_t)(m0 + rA + 64) * K + cA);
    float4 pb  = *(const float4*)(B + (size_t)(n0 + rB) * K + cB);

    const int nk = K / BK;
    for (int t = 0; t < nk; t++) {
        const int buf = t & 1;
        As[buf][cA + 0][rA] = pa0.x; As[buf][cA + 1][rA] = pa0.y;
        As[buf][cA + 2][rA] = pa0.z; As[buf][cA + 3][rA] = pa0.w;
        As[buf][cA + 0][rA + 64] = pa1.x; As[buf][cA + 1][rA + 64] = pa1.y;
        As[buf][cA + 2][rA + 64] = pa1.z; As[buf][cA + 3][rA + 64] = pa1.w;
        Bs[buf][cB + 0][rB] = pb.x; Bs[buf][cB + 1][rB] = pb.y;
        Bs[buf][cB + 2][rB] = pb.z; Bs[buf][cB + 3][rB] = pb.w;
        __syncthreads();
        if (t + 1 < nk) {
            int k0 = (t + 1) * BK;
            pa0 = *(const float4*)(A + (size_t)(m0 + rA) * K + k0 + cA);
            pa1 = *(const float4*)(A + (size_t)(m0 + rA + 64) * K + k0 + cA);
            pb  = *(const float4*)(B + (size_t)(n0 + rB) * K + k0 + cB);
        }
#pragma unroll
        for (int kk = 0; kk < BK; kk++) {
            float4 a0 = *(const float4*)&As[buf][kk][ty * 8];
            float4 a1 = *(const float4*)&As[buf][kk][ty * 8 + 4];
            ulonglong2 b = *(const ulonglong2*)&Bs[buf][kk][tx * 4];
            u64 ad;
            ad = dup2(a0.x); fma2(acc[0][0], ad, b.x); fma2(acc[0][1], ad, b.y);
            ad = dup2(a0.y); fma2(acc[1][0], ad, b.x); fma2(acc[1][1], ad, b.y);
            ad = dup2(a0.z); fma2(acc[2][0], ad, b.x); fma2(acc[2][1], ad, b.y);
            ad = dup2(a0.w); fma2(acc[3][0], ad, b.x); fma2(acc[3][1], ad, b.y);
            ad = dup2(a1.x); fma2(acc[4][0], ad, b.x); fma2(acc[4][1], ad, b.y);
            ad = dup2(a1.y); fma2(acc[5][0], ad, b.x); fma2(acc[5][1], ad, b.y);
            ad = dup2(a1.z); fma2(acc[6][0], ad, b.x); fma2(acc[6][1], ad, b.y);
            ad = dup2(a1.w); fma2(acc[7][0], ad, b.x); fma2(acc[7][1], ad, b.y);
        }
    }

    // epilogue: optional per-head LayerNorm, then store
    const bool doln = (blockIdx.z < 2);
    float4 wv = {0, 0, 0, 0}, bv = {0, 0, 0, 0};
    if (doln) {
        const float* w  = (blockIdx.z == 0) ? qw : kw;
        const float* bb = (blockIdx.z == 0) ? qb : kb;
        wv = *(const float4*)&w[tx * 4];
        bv = *(const float4*)&bb[tx * 4];
    }
#pragma unroll
    for (int i = 0; i < 8; i++) {
        float x0, x1, x2, x3;
        unpk2(acc[i][0], x0, x1);
        unpk2(acc[i][1], x2, x3);
        if (doln) {
            float s = x0 + x1 + x2 + x3;
#pragma unroll
            for (int off = 8; off; off >>= 1) s += __shfl_xor_sync(~0u, s, off, 16);
            float mu = s * (1.f / 64.f);
            float d0 = x0 - mu, d1 = x1 - mu, d2 = x2 - mu, d3 = x3 - mu;
            float q = d0 * d0 + d1 * d1 + d2 * d2 + d3 * d3;
#pragma unroll
            for (int off = 8; off; off >>= 1) q += __shfl_xor_sync(~0u, q, off, 16);
            float rs = rsqrtf(q * (1.f / 64.f) + LN_EPS);
            x0 = d0 * rs * wv.x + bv.x;
            x1 = d1 * rs * wv.y + bv.y;
            x2 = d2 * rs * wv.z + bv.z;
            x3 = d3 * rs * wv.w + bv.w;
        }
        size_t off = (size_t)(m0 + ty * 8 + i) * N + n0 + tx * 4;
        *(float4*)(C + off) = make_float4(x0, x1, x2, x3);
    }
}

// ---------------- flash attention v5 (R10 form): QT=128, KT=64 --------------
#define QT 128
#define KT 64
#define QS_ST 132
#define KS_ST 68
#define VS_ST 68
#define PS_ST 132
#define OFF_KS (64*QS_ST)
#define OFF_VS (OFF_KS + 64*KS_ST)
#define OFF_PS (OFF_VS + KT*VS_ST)
#define ATTN_SMEM ((OFF_PS + KT*PS_ST) * 4)

__global__ __launch_bounds__(256, 2) void attn_kernel(const float* __restrict__ Qg,
                                                      const float* __restrict__ Kg,
                                                      const float* __restrict__ Vg) {
    extern __shared__ float sm[];
    float* Qs = sm;              // [k=64][m=128+4]
    float* Ks = sm + OFF_KS;     // [k=64][j=64+4]
    float* Vs = sm + OFF_VS;     // [c=64][d=64+4]
    float* Ps = sm + OFF_PS;     // [c=64][m=128+4]

    const int qt = blockIdx.x, h = blockIdx.y, b = blockIdx.z;
    const int tid = threadIdx.x;
    const int tx = tid & 15, ty = tid >> 4;
    const int q0 = qt * QT;
    const float scale = 0.125f;

    const float* qp = Qg + (size_t)(b * Sx + q0) * Hx + h * HD;
#pragma unroll
    for (int it = 0; it < 8; it++) {
        int idx = tid + it * 256;
        int r = idx >> 4, c4 = (idx & 15) * 4;
        float4 v = *(const float4*)(qp + (size_t)r * Hx + c4);
        Qs[(c4 + 0) * QS_ST + r] = v.x * scale;
        Qs[(c4 + 1) * QS_ST + r] = v.y * scale;
        Qs[(c4 + 2) * QS_ST + r] = v.z * scale;
        Qs[(c4 + 3) * QS_ST + r] = v.w * scale;
    }

    u64 acc2[4][4];
    u64 l2[4];
#pragma unroll
    for (int ip = 0; ip < 4; ip++) {
        l2[ip] = 0ull;
#pragma unroll
        for (int dd = 0; dd < 4; dd++) acc2[ip][dd] = 0ull;
    }

    for (int kt = 0; kt < Sx / KT; kt++) {
        __syncthreads();
        const float* kp = Kg + (size_t)(b * Sx + kt * KT) * Hx + h * HD;
        const float* vp = Vg + (size_t)(b * Sx + kt * KT) * Hx + h * HD;
#pragma unroll
        for (int it = 0; it < 4; it++) {
            int idx = tid + it * 256;
            int r = idx >> 4, c4 = (idx & 15) * 4;
            float4 kv = *(const float4*)(kp + (size_t)r * Hx + c4);
            Ks[(c4 + 0) * KS_ST + r] = kv.x;
            Ks[(c4 + 1) * KS_ST + r] = kv.y;
            Ks[(c4 + 2) * KS_ST + r] = kv.z;
            Ks[(c4 + 3) * KS_ST + r] = kv.w;
            float4 vv = *(const float4*)(vp + (size_t)r * Hx + c4);
            *(float4*)&Vs[r * VS_ST + c4] = vv;
        }
        __syncthreads();

        u64 s2[4][4];
#pragma unroll
        for (int ip = 0; ip < 4; ip++)
#pragma unroll
            for (int j = 0; j < 4; j++) s2[ip][j] = 0ull;
#pragma unroll 16
        for (int kk = 0; kk < 64; kk++) {
            ulonglong2 q01 = *(const ulonglong2*)&Qs[kk * QS_ST + ty * 8];
            ulonglong2 q23 = *(const ulonglong2*)&Qs[kk * QS_ST + ty * 8 + 4];
            float4 k4 = *(const float4*)&Ks[kk * KS_ST + tx * 4];
            u64 kd;
            kd = dup2(k4.x);
            fma2(s2[0][0], q01.x, kd); fma2(s2[1][0], q01.y, kd);
            fma2(s2[2][0], q23.x, kd); fma2(s2[3][0], q23.y, kd);
            kd = dup2(k4.y);
            fma2(s2[0][1], q01.x, kd); fma2(s2[1][1], q01.y, kd);
            fma2(s2[2][1], q23.x, kd); fma2(s2[3][1], q23.y, kd);
            kd = dup2(k4.z);
            fma2(s2[0][2], q01.x, kd); fma2(s2[1][2], q01.y, kd);
            fma2(s2[2][2], q23.x, kd); fma2(s2[3][2], q23.y, kd);
            kd = dup2(k4.w);
            fma2(s2[0][3], q01.x, kd); fma2(s2[1][3], q01.y, kd);
            fma2(s2[2][3], q23.x, kd); fma2(s2[3][3], q23.y, kd);
        }

#pragma unroll
        for (int ip = 0; ip < 4; ip++) {
#pragma unroll
            for (int j = 0; j < 4; j++) {
                float f0, f1;
                unpk2(s2[ip][j], f0, f1);
                u64 pr = pack2(__expf(f0), __expf(f1));
                add2(l2[ip], pr);
                *(u64*)&Ps[(tx * 4 + j) * PS_ST + ty * 8 + 2 * ip] = pr;
            }
        }
        __syncthreads();

#pragma unroll 8
        for (int c = 0; c < KT; c++) {
            ulonglong2 pA = *(const ulonglong2*)&Ps[c * PS_ST + ty * 8];
            ulonglong2 pB = *(const ulonglong2*)&Ps[c * PS_ST + ty * 8 + 4];
            float4 vv = *(const float4*)&Vs[c * VS_ST + tx * 4];
            u64 vd;
            vd = dup2(vv.x);
            fma2(acc2[0][0], pA.x, vd); fma2(acc2[1][0], pA.y, vd);
            fma2(acc2[2][0], pB.x, vd); fma2(acc2[3][0], pB.y, vd);
            vd = dup2(vv.y);
            fma2(acc2[0][1], pA.x, vd); fma2(acc2[1][1], pA.y, vd);
            fma2(acc2[2][1], pB.x, vd); fma2(acc2[3][1], pB.y, vd);
            vd = dup2(vv.z);
            fma2(acc2[0][2], pA.x, vd); fma2(acc2[1][2], pA.y, vd);
            fma2(acc2[2][2], pB.x, vd); fma2(acc2[3][2], pB.y, vd);
            vd = dup2(vv.w);
            fma2(acc2[0][3], pA.x, vd); fma2(acc2[1][3], pA.y, vd);
            fma2(acc2[2][3], pB.x, vd); fma2(acc2[3][3], pB.y, vd);
        }
    }

#pragma unroll
    for (int ip = 0; ip < 4; ip++) {
#pragma unroll
        for (int off = 8; off; off >>= 1) {
            u64 o = __shfl_xor_sync(~0u, l2[ip], off, 16);
            add2(l2[ip], o);
        }
    }

    float* ob = g_ctx + ((size_t)(b * NH + h) * Sx + q0) * HD;
#pragma unroll
    for (int ip = 0; ip < 4; ip++) {
        float la, lb;
        unpk2(l2[ip], la, lb);
        float ia = 1.f / la, ib = 1.f / lb;
        float4 r0, r1;
        float x, y;
        unpk2(acc2[ip][0], x, y); r0.x = x * ia; r1.x = y * ib;
        unpk2(acc2[ip][1], x, y); r0.y = x * ia; r1.y = y * ib;
        unpk2(acc2[ip][2], x, y); r0.z = x * ia; r1.z = y * ib;
        unpk2(acc2[ip][3], x, y); r0.w = x * ia; r1.w = y * ib;
        *(float4*)(ob + (size_t)(ty * 8 + 2 * ip) * HD + tx * 4)     = r0;
        *(float4*)(ob + (size_t)(ty * 8 + 2 * ip + 1) * HD + tx * 4) = r1;
    }
}

// ---------------- z = mixed-context . vw  ------------------------------------
__global__ __launch_bounds__(256) void z_kernel() {
    __shared__ float cs[128][65];
    __shared__ float vws[NH * HD];
    int t = threadIdx.x;
    int n = blockIdx.y, m0 = blockIdx.x * 128;
    for (int i = t; i < NH * HD; i += 256) vws[i] = g_vw[i];
    int b = n >> 4, hi = n & 15;
#pragma unroll 8
    for (int it = 0; it < 32; it++) {
        int f = t + it * 256;
        int j = f >> 6, d = f & 63;
        int m = m0 + j;
        int t2 = hi * Sx + m;
        int s = t2 >> 4, hh = t2 & 15;
        cs[j][d] = g_ctx[((size_t)(b * NH + hh) * Sx + s) * HD + d];
    }
    __syncthreads();
#pragma unroll 1
    for (int p = 0; p < 8; p++) {
        int h2 = p * 2 + (t >> 7);
        int ml = t & 127;
        const float* vr = &vws[h2 * HD];
        float a = 0.f;
#pragma unroll
        for (int d = 0; d < 64; d++) a += cs[ml][d] * vr[d];
        g_z[((size_t)n * 16 + h2) * Sx + m0 + ml] = a;
    }
}

// ---------------- top-128 threshold per row ----------------------------------
__global__ __launch_bounds__(256) void topk_kernel() {
    int row = blockIdx.x, t = threadIdx.x;
    const float* zr = g_z + (size_t)row * Sx;
    unsigned v[8];
#pragma unroll
    for (int i = 0; i < 8; i++) v[i] = f2ord(zr[t + i * 256]);
    __shared__ int scnt;
    unsigned lo = 0u, hi = 0xFFFFFFFFu;
    while (lo < hi) {
        unsigned mid = lo + ((hi - lo) >> 1);
        int c = 0;
#pragma unroll
        for (int i = 0; i < 8; i++) c += (v[i] > mid);
#pragma unroll
        for (int off = 16; off; off >>= 1) c += __shfl_xor_sync(~0u, c, off);
        __syncthreads();
        if (t == 0) scnt = 0;
        __syncthreads();
        if ((t & 31) == 0) atomicAdd(&scnt, c);
        __syncthreads();
        int tot = scnt;
        if (tot >= TOPK) lo = mid + 1; else hi = mid;
    }
    if (t == 0) g_thr[row] = lo;
}

// ---------------- fused y+WO GEMM: out[s,o] = sum_hh2 zsr[s][hh2]*W2[o][hh2] -
// A = thresholded g_z (naturally k-major: row hh2, contiguous in s),
// B = g_W2 [1024][256]. M=128 (s), N=64 (o), K=256. grid (16, 16, B).
#define ZBK 16

__global__ __launch_bounds__(256, 3) void zw_gemm(float* __restrict__ out) {
    __shared__ float As[ZBK][128 + 4];   // [k][m]
    __shared__ float Bs[ZBK][64 + 4];    // [k][n]
    const int tid = threadIdx.x;
    const int tx = tid & 15, ty = tid >> 4;
    const int n0 = blockIdx.x * 64, s0 = blockIdx.y * 128, b = blockIdx.z;

    u64 acc[8][2];
#pragma unroll
    for (int i = 0; i < 8; i++) { acc[i][0] = 0ull; acc[i][1] = 0ull; }

    const int rB = tid >> 2, cB = (tid & 3) * 4;

    for (int kc = 0; kc < 256 / ZBK; kc++) {
        const int k0 = kc * ZBK;
        __syncthreads();
        // A: 16 k-rows x 128 s (thresholded z), 512 float4 chunks
#pragma unroll
        for (int it = 0; it < 2; it++) {
            int idx = tid + it * 256;
            int r = idx >> 5, c4 = (idx & 31) * 4;
            int krow = b * 256 + k0 + r;
            unsigned th = g_thr[krow];
            float4 v = *(const float4*)(g_z + (size_t)krow * Sx + s0 + c4);
            v.x = (f2ord(v.x) >= th) ? v.x : 0.f;
            v.y = (f2ord(v.y) >= th) ? v.y : 0.f;
            v.z = (f2ord(v.z) >= th) ? v.z : 0.f;
            v.w = (f2ord(v.w) >= th) ? v.w : 0.f;
            *(float4*)&As[r][c4] = v;
        }
        // B: 64 o-rows x 16 k -> transpose to k-major
        {
            float4 w = *(const float4*)(g_W2 + (size_t)(n0 + rB) * 256 + k0 + cB);
            Bs[cB + 0][rB] = w.x; Bs[cB + 1][rB] = w.y;
            Bs[cB + 2][rB] = w.z; Bs[cB + 3][rB] = w.w;
        }
        __syncthreads();
#pragma unroll
        for (int kk = 0; kk < ZBK; kk++) {
            float4 a0 = *(const float4*)&As[kk][ty * 8];
            float4 a1 = *(const float4*)&As[kk][ty * 8 + 4];
            ulonglong2 bq = *(const ulonglong2*)&Bs[kk][tx * 4];
            u64 ad;
            ad = dup2(a0.x); fma2(acc[0][0], ad, bq.x); fma2(acc[0][1], ad, bq.y);
            ad = dup2(a0.y); fma2(acc[1][0], ad, bq.x); fma2(acc[1][1], ad, bq.y);
            ad = dup2(a0.z); fma2(acc[2][0], ad, bq.x); fma2(acc[2][1], ad, bq.y);
            ad = dup2(a0.w); fma2(acc[3][0], ad, bq.x); fma2(acc[3][1], ad, bq.y);
            ad = dup2(a1.x); fma2(acc[4][0], ad, bq.x); fma2(acc[4][1], ad, bq.y);
            ad = dup2(a1.y); fma2(acc[5][0], ad, bq.x); fma2(acc[5][1], ad, bq.y);
            ad = dup2(a1.z); fma2(acc[6][0], ad, bq.x); fma2(acc[6][1], ad, bq.y);
            ad = dup2(a1.w); fma2(acc[7][0], ad, bq.x); fma2(acc[7][1], ad, bq.y);
        }
    }
#pragma unroll
    for (int i = 0; i < 8; i++) {
        size_t off = (size_t)(b * Sx + s0 + ty * 8 + i) * Hx + n0 + tx * 4;
        ulonglong2 s = {acc[i][0], acc[i][1]};
        *(ulonglong2*)(out + off) = s;
    }
}

// ---------------- reduce sparse weight means ---------------------------------
__global__ void prep_kernel(const float* __restrict__ swv,
                            const float* __restrict__ swo) {
    int t = blockIdx.x * 64 + threadIdx.x;
    int h = t >> 6, d = t & 63;
    float s1 = 0.f, s2 = 0.f;
#pragma unroll 4
    for (int k = 0; k < 128; k++) {
        s1 += swv[((size_t)(h * 64 + d)) * 128 + k];
        s2 += swo[((size_t)(h * 128 + k)) * 64 + d];
    }
    g_vw[t] = s1 * (1.f / 128.f);
    g_ow[t] = s2 * (1.f / 128.f);
}

// ---------------- W2[o][h*16+h2] = sum_d ow[h2,d] * WO[o, h*64+d] -----------
__global__ void prep2_kernel(const float* __restrict__ WO) {
    int o = blockIdx.x, t = threadIdx.x;   // t = h*16+h2
    int h = t >> 4, h2 = t & 15;
    const float* wo = WO + (size_t)o * Hx + h * 64;
    const float* ow = g_ow + h2 * 64;
    float s = 0.f;
#pragma unroll 8
    for (int d = 0; d < 64; d++) s += ow[d] * wo[d];
    g_W2[(size_t)o * 256 + t] = s;
}

// ---------------- launch ----------------------------------------------------
extern "C" void kernel_launch(void* const* d_in, const int* in_sizes, int n_in,
                              void* d_out, int out_size) {
    const float* x   = (const float*)d_in[0];
    const float* WQ  = (const float*)d_in[1];
    const float* WK  = (const float*)d_in[2];
    const float* WV  = (const float*)d_in[3];
    const float* WO  = (const float*)d_in[4];
    const float* qw  = (const float*)d_in[5];
    const float* qb  = (const float*)d_in[6];
    const float* kw  = (const float*)d_in[7];
    const float* kb  = (const float*)d_in[8];
    const float* swv = (const float*)d_in[9];
    const float* swo = (const float*)d_in[10];
    float* out = (float*)d_out;

    float *pQ, *pK, *pV;
    cudaGetSymbolAddress((void**)&pQ, g_Q);
    cudaGetSymbolAddress((void**)&pK, g_K);
    cudaGetSymbolAddress((void**)&pV, g_V);

    cudaFuncSetAttribute(attn_kernel,
                         cudaFuncAttributeMaxDynamicSharedMemorySize, ATTN_SMEM);

    prep_kernel<<<16, 64>>>(swv, swo);
    prep2_kernel<<<1024, 256>>>(WO);

    // fused QKV projection with LN epilogue (z: 0=Q, 1=K, 2=V)
    sgemm_qkv<<<dim3(Hx / BN, BSx / BM, 3), 256>>>(
        x, WQ, WK, WV, pQ, pK, pV, qw, qb, kw, kb, BSx, Hx, Hx);

    attn_kernel<<<dim3(Sx / QT, NH, Bx), 256, ATTN_SMEM>>>(pQ, pK, pV);

    z_kernel<<<dim3(Sx / 128, 32), 256>>>();
    topk_kernel<<<512, 256>>>();

    // fused y + W_O projection via pre-contracted W2
    zw_gemm<<<dim3(Hx / 64, Sx / 128, Bx), 256>>>(out);
}

// round 14
// speedup vs baseline: 1.1346x; 1.0159x over previous
#include <cuda_runtime.h>
#include <cstdint>
#include <cstddef>

// ---------------- problem constants ----------------
#define Bx 2
#define Sx 2048
#define Hx 1024
#define NH 16
#define HD 64
#define BSx (Bx*Sx)          // 4096
#define TOPK 128
#define LN_EPS 1e-5f

typedef unsigned long long u64;

// ---------------- packed f32x2 helpers ----------------
__device__ __forceinline__ u64 pack2(float x, float y) {
    u64 r; asm("mov.b64 %0,{%1,%2};" : "=l"(r) : "f"(x), "f"(y)); return r;
}
__device__ __forceinline__ u64 dup2(float x) { return pack2(x, x); }
__device__ __forceinline__ void unpk2(u64 v, float& x, float& y) {
    asm("mov.b64 {%0,%1},%2;" : "=f"(x), "=f"(y) : "l"(v));
}
__device__ __forceinline__ void fma2(u64& d, u64 a, u64 b) {
    asm("fma.rn.f32x2 %0,%1,%2,%0;" : "+l"(d) : "l"(a), "l"(b));
}
__device__ __forceinline__ void mul2(u64& d, u64 a) {
    asm("mul.rn.f32x2 %0,%0,%1;" : "+l"(d) : "l"(a));
}
__device__ __forceinline__ void add2(u64& d, u64 a) {
    asm("add.rn.f32x2 %0,%0,%1;" : "+l"(d) : "l"(a));
}
__device__ __forceinline__ void sub2(u64& d, u64 a) {
    asm("sub.rn.f32x2 %0,%0,%1;" : "+l"(d) : "l"(a));
}

// ---------------- scratch (device globals; no allocation) ----------------
__device__ float    g_Q[BSx*Hx];
__device__ float    g_K[BSx*Hx];
__device__ float    g_V[BSx*Hx];
__device__ float    g_ctx[BSx*Hx];
__device__ float    g_z[32*16*2048];
__device__ unsigned g_thr[32*16];
__device__ float    g_vw[NH*HD];
__device__ float    g_ow[NH*HD];
__device__ float    g_W2[Hx*256];

__device__ __forceinline__ unsigned f2ord(float f) {
    unsigned u = __float_as_uint(f);
    return (u >> 31) ? ~u : (u | 0x80000000u);
}

// ---------------- SGEMM (NT) row-paired + fused LN epilogue ------------------
// C[M,N] = A[M,K] * B[N,K]^T. 128x64 tile, double-buffered, 3 CTAs/SM.
// Accumulators pair along M: acc2[ip][j] = rows (ty*8+2ip, +1), col tx*4+j.
// Inner loop: 3 LDS + 4 dup + 16 fma2 (was 3+8+16).
// blockIdx.z: 0=Q (LN), 1=K (LN), 2=V (no LN).
#define BM 128
#define BN 64
#define BK 16

__global__ __launch_bounds__(256, 3) void sgemm_qkv(
    const float* __restrict__ A,
    const float* __restrict__ B0, const float* __restrict__ B1,
    const float* __restrict__ B2,
    float* __restrict__ C0, float* __restrict__ C1, float* __restrict__ C2,
    const float* __restrict__ qw, const float* __restrict__ qb,
    const float* __restrict__ kw, const float* __restrict__ kb,
    int M, int N, int K) {
    __shared__ float As[2][BK][BM + 4];   // k-major ping-pong
    __shared__ float Bs[2][BK][BN + 4];
    const int tid = threadIdx.x;
    const int tx = tid & 15, ty = tid >> 4;
    const int n0 = blockIdx.x * BN, m0 = blockIdx.y * BM;

    const float* B = (blockIdx.z == 0) ? B0 : (blockIdx.z == 1) ? B1 : B2;
    float*       C = (blockIdx.z == 0) ? C0 : (blockIdx.z == 1) ? C1 : C2;

    u64 acc2[4][4];
#pragma unroll
    for (int ip = 0; ip < 4; ip++)
#pragma unroll
        for (int j = 0; j < 4; j++) acc2[ip][j] = 0ull;

    const int rA = tid >> 2, cA = (tid & 3) * 4;
    const int rB = tid >> 2, cB = (tid & 3) * 4;

    float4 pa0 = *(const float4*)(A + (size_t)(m0 + rA) * K + cA);
    float4 pa1 = *(const float4*)(A + (size_t)(m0 + rA + 64) * K + cA);
    float4 pb  = *(const float4*)(B + (size_t)(n0 + rB) * K + cB);

    const int nk = K / BK;
    for (int t = 0; t < nk; t++) {
        const int buf = t & 1;
        As[buf][cA + 0][rA] = pa0.x; As[buf][cA + 1][rA] = pa0.y;
        As[buf][cA + 2][rA] = pa0.z; As[buf][cA + 3][rA] = pa0.w;
        As[buf][cA + 0][rA + 64] = pa1.x; As[buf][cA + 1][rA + 64] = pa1.y;
        As[buf][cA + 2][rA + 64] = pa1.z; As[buf][cA + 3][rA + 64] = pa1.w;
        Bs[buf][cB + 0][rB] = pb.x; Bs[buf][cB + 1][rB] = pb.y;
        Bs[buf][cB + 2][rB] = pb.z; Bs[buf][cB + 3][rB] = pb.w;
        __syncthreads();
        if (t + 1 < nk) {
            int k0 = (t + 1) * BK;
            pa0 = *(const float4*)(A + (size_t)(m0 + rA) * K + k0 + cA);
            pa1 = *(const float4*)(A + (size_t)(m0 + rA + 64) * K + k0 + cA);
            pb  = *(const float4*)(B + (size_t)(n0 + rB) * K + k0 + cB);
        }
#pragma unroll
        for (int kk = 0; kk < BK; kk++) {
            ulonglong2 q01 = *(const ulonglong2*)&As[buf][kk][ty * 8];
            ulonglong2 q23 = *(const ulonglong2*)&As[buf][kk][ty * 8 + 4];
            float4 b4 = *(const float4*)&Bs[buf][kk][tx * 4];
            u64 bd;
            bd = dup2(b4.x);
            fma2(acc2[0][0], q01.x, bd); fma2(acc2[1][0], q01.y, bd);
            fma2(acc2[2][0], q23.x, bd); fma2(acc2[3][0], q23.y, bd);
            bd = dup2(b4.y);
            fma2(acc2[0][1], q01.x, bd); fma2(acc2[1][1], q01.y, bd);
            fma2(acc2[2][1], q23.x, bd); fma2(acc2[3][1], q23.y, bd);
            bd = dup2(b4.z);
            fma2(acc2[0][2], q01.x, bd); fma2(acc2[1][2], q01.y, bd);
            fma2(acc2[2][2], q23.x, bd); fma2(acc2[3][2], q23.y, bd);
            bd = dup2(b4.w);
            fma2(acc2[0][3], q01.x, bd); fma2(acc2[1][3], q01.y, bd);
            fma2(acc2[2][3], q23.x, bd); fma2(acc2[3][3], q23.y, bd);
        }
    }

    // epilogue: optional paired per-head LayerNorm, then store row-pairs.
    const bool doln = (blockIdx.z < 2);
    float4 wv = {0, 0, 0, 0}, bv = {0, 0, 0, 0};
    if (doln) {
        const float* w  = (blockIdx.z == 0) ? qw : kw;
        const float* bb = (blockIdx.z == 0) ? qb : kb;
        wv = *(const float4*)&w[tx * 4];
        bv = *(const float4*)&bb[tx * 4];
    }
#pragma unroll
    for (int ip = 0; ip < 4; ip++) {
        u64 v0 = acc2[ip][0], v1 = acc2[ip][1], v2 = acc2[ip][2], v3 = acc2[ip][3];
        if (doln) {
            // paired row sums over 64 cols (4 local + 16-lane tx group)
            u64 s2 = v0; add2(s2, v1); add2(s2, v2); add2(s2, v3);
#pragma unroll
            for (int off = 8; off; off >>= 1) {
                u64 o = __shfl_xor_sync(~0u, s2, off, 16);
                add2(s2, o);
            }
            u64 mu2 = s2; mul2(mu2, dup2(1.f / 64.f));
            sub2(v0, mu2); sub2(v1, mu2); sub2(v2, mu2); sub2(v3, mu2);
            u64 q2 = 0ull;
            fma2(q2, v0, v0); fma2(q2, v1, v1);
            fma2(q2, v2, v2); fma2(q2, v3, v3);
#pragma unroll
            for (int off = 8; off; off >>= 1) {
                u64 o = __shfl_xor_sync(~0u, q2, off, 16);
                add2(q2, o);
            }
            float qa, qb2;
            unpk2(q2, qa, qb2);
            u64 rs2 = pack2(rsqrtf(qa * (1.f / 64.f) + LN_EPS),
                            rsqrtf(qb2 * (1.f / 64.f) + LN_EPS));
            mul2(v0, rs2); mul2(v1, rs2); mul2(v2, rs2); mul2(v3, rs2);
            // x*w + b per column (w,b same for both rows of the pair)
            u64 t;
            t = dup2(bv.x); fma2(t, v0, dup2(wv.x)); v0 = t;
            t = dup2(bv.y); fma2(t, v1, dup2(wv.y)); v1 = t;
            t = dup2(bv.z); fma2(t, v2, dup2(wv.z)); v2 = t;
            t = dup2(bv.w); fma2(t, v3, dup2(wv.w)); v3 = t;
        }
        float x0, y0, x1, y1, x2, y2, x3, y3;
        unpk2(v0, x0, y0); unpk2(v1, x1, y1);
        unpk2(v2, x2, y2); unpk2(v3, x3, y3);
        size_t off0 = (size_t)(m0 + ty * 8 + 2 * ip) * N + n0 + tx * 4;
        size_t off1 = off0 + N;
        *(float4*)(C + off0) = make_float4(x0, x1, x2, x3);
        *(float4*)(C + off1) = make_float4(y0, y1, y2, y3);
    }
}

// ---------------- flash attention v5 (R10 form): QT=128, KT=64 --------------
#define QT 128
#define KT 64
#define QS_ST 132
#define KS_ST 68
#define VS_ST 68
#define PS_ST 132
#define OFF_KS (64*QS_ST)
#define OFF_VS (OFF_KS + 64*KS_ST)
#define OFF_PS (OFF_VS + KT*VS_ST)
#define ATTN_SMEM ((OFF_PS + KT*PS_ST) * 4)

__global__ __launch_bounds__(256, 2) void attn_kernel(const float* __restrict__ Qg,
                                                      const float* __restrict__ Kg,
                                                      const float* __restrict__ Vg) {
    extern __shared__ float sm[];
    float* Qs = sm;
    float* Ks = sm + OFF_KS;
    float* Vs = sm + OFF_VS;
    float* Ps = sm + OFF_PS;

    const int qt = blockIdx.x, h = blockIdx.y, b = blockIdx.z;
    const int tid = threadIdx.x;
    const int tx = tid & 15, ty = tid >> 4;
    const int q0 = qt * QT;
    const float scale = 0.125f;

    const float* qp = Qg + (size_t)(b * Sx + q0) * Hx + h * HD;
#pragma unroll
    for (int it = 0; it < 8; it++) {
        int idx = tid + it * 256;
        int r = idx >> 4, c4 = (idx & 15) * 4;
        float4 v = *(const float4*)(qp + (size_t)r * Hx + c4);
        Qs[(c4 + 0) * QS_ST + r] = v.x * scale;
        Qs[(c4 + 1) * QS_ST + r] = v.y * scale;
        Qs[(c4 + 2) * QS_ST + r] = v.z * scale;
        Qs[(c4 + 3) * QS_ST + r] = v.w * scale;
    }

    u64 acc2[4][4];
    u64 l2[4];
#pragma unroll
    for (int ip = 0; ip < 4; ip++) {
        l2[ip] = 0ull;
#pragma unroll
        for (int dd = 0; dd < 4; dd++) acc2[ip][dd] = 0ull;
    }

    for (int kt = 0; kt < Sx / KT; kt++) {
        __syncthreads();
        const float* kp = Kg + (size_t)(b * Sx + kt * KT) * Hx + h * HD;
        const float* vp = Vg + (size_t)(b * Sx + kt * KT) * Hx + h * HD;
#pragma unroll
        for (int it = 0; it < 4; it++) {
            int idx = tid + it * 256;
            int r = idx >> 4, c4 = (idx & 15) * 4;
            float4 kv = *(const float4*)(kp + (size_t)r * Hx + c4);
            Ks[(c4 + 0) * KS_ST + r] = kv.x;
            Ks[(c4 + 1) * KS_ST + r] = kv.y;
            Ks[(c4 + 2) * KS_ST + r] = kv.z;
            Ks[(c4 + 3) * KS_ST + r] = kv.w;
            float4 vv = *(const float4*)(vp + (size_t)r * Hx + c4);
            *(float4*)&Vs[r * VS_ST + c4] = vv;
        }
        __syncthreads();

        u64 s2[4][4];
#pragma unroll
        for (int ip = 0; ip < 4; ip++)
#pragma unroll
            for (int j = 0; j < 4; j++) s2[ip][j] = 0ull;
#pragma unroll 16
        for (int kk = 0; kk < 64; kk++) {
            ulonglong2 q01 = *(const ulonglong2*)&Qs[kk * QS_ST + ty * 8];
            ulonglong2 q23 = *(const ulonglong2*)&Qs[kk * QS_ST + ty * 8 + 4];
            float4 k4 = *(const float4*)&Ks[kk * KS_ST + tx * 4];
            u64 kd;
            kd = dup2(k4.x);
            fma2(s2[0][0], q01.x, kd); fma2(s2[1][0], q01.y, kd);
            fma2(s2[2][0], q23.x, kd); fma2(s2[3][0], q23.y, kd);
            kd = dup2(k4.y);
            fma2(s2[0][1], q01.x, kd); fma2(s2[1][1], q01.y, kd);
            fma2(s2[2][1], q23.x, kd); fma2(s2[3][1], q23.y, kd);
            kd = dup2(k4.z);
            fma2(s2[0][2], q01.x, kd); fma2(s2[1][2], q01.y, kd);
            fma2(s2[2][2], q23.x, kd); fma2(s2[3][2], q23.y, kd);
            kd = dup2(k4.w);
            fma2(s2[0][3], q01.x, kd); fma2(s2[1][3], q01.y, kd);
            fma2(s2[2][3], q23.x, kd); fma2(s2[3][3], q23.y, kd);
        }

#pragma unroll
        for (int ip = 0; ip < 4; ip++) {
#pragma unroll
            for (int j = 0; j < 4; j++) {
                float f0, f1;
                unpk2(s2[ip][j], f0, f1);
                u64 pr = pack2(__expf(f0), __expf(f1));
                add2(l2[ip], pr);
                *(u64*)&Ps[(tx * 4 + j) * PS_ST + ty * 8 + 2 * ip] = pr;
            }
        }
        __syncthreads();

#pragma unroll 8
        for (int c = 0; c < KT; c++) {
            ulonglong2 pA = *(const ulonglong2*)&Ps[c * PS_ST + ty * 8];
            ulonglong2 pB = *(const ulonglong2*)&Ps[c * PS_ST + ty * 8 + 4];
            float4 vv = *(const float4*)&Vs[c * VS_ST + tx * 4];
            u64 vd;
            vd = dup2(vv.x);
            fma2(acc2[0][0], pA.x, vd); fma2(acc2[1][0], pA.y, vd);
            fma2(acc2[2][0], pB.x, vd); fma2(acc2[3][0], pB.y, vd);
            vd = dup2(vv.y);
            fma2(acc2[0][1], pA.x, vd); fma2(acc2[1][1], pA.y, vd);
            fma2(acc2[2][1], pB.x, vd); fma2(acc2[3][1], pB.y, vd);
            vd = dup2(vv.z);
            fma2(acc2[0][2], pA.x, vd); fma2(acc2[1][2], pA.y, vd);
            fma2(acc2[2][2], pB.x, vd); fma2(acc2[3][2], pB.y, vd);
            vd = dup2(vv.w);
            fma2(acc2[0][3], pA.x, vd); fma2(acc2[1][3], pA.y, vd);
            fma2(acc2[2][3], pB.x, vd); fma2(acc2[3][3], pB.y, vd);
        }
    }

#pragma unroll
    for (int ip = 0; ip < 4; ip++) {
#pragma unroll
        for (int off = 8; off; off >>= 1) {
            u64 o = __shfl_xor_sync(~0u, l2[ip], off, 16);
            add2(l2[ip], o);
        }
    }

    float* ob = g_ctx + ((size_t)(b * NH + h) * Sx + q0) * HD;
#pragma unroll
    for (int ip = 0; ip < 4; ip++) {
        float la, lb;
        unpk2(l2[ip], la, lb);
        float ia = 1.f / la, ib = 1.f / lb;
        float4 r0, r1;
        float x, y;
        unpk2(acc2[ip][0], x, y); r0.x = x * ia; r1.x = y * ib;
        unpk2(acc2[ip][1], x, y); r0.y = x * ia; r1.y = y * ib;
        unpk2(acc2[ip][2], x, y); r0.z = x * ia; r1.z = y * ib;
        unpk2(acc2[ip][3], x, y); r0.w = x * ia; r1.w = y * ib;
        *(float4*)(ob + (size_t)(ty * 8 + 2 * ip) * HD + tx * 4)     = r0;
        *(float4*)(ob + (size_t)(ty * 8 + 2 * ip + 1) * HD + tx * 4) = r1;
    }
}

// ---------------- z = mixed-context . vw  ------------------------------------
__global__ __launch_bounds__(256) void z_kernel() {
    __shared__ float cs[128][65];
    __shared__ float vws[NH * HD];
    int t = threadIdx.x;
    int n = blockIdx.y, m0 = blockIdx.x * 128;
    for (int i = t; i < NH * HD; i += 256) vws[i] = g_vw[i];
    int b = n >> 4, hi = n & 15;
#pragma unroll 8
    for (int it = 0; it < 32; it++) {
        int f = t + it * 256;
        int j = f >> 6, d = f & 63;
        int m = m0 + j;
        int t2 = hi * Sx + m;
        int s = t2 >> 4, hh = t2 & 15;
        cs[j][d] = g_ctx[((size_t)(b * NH + hh) * Sx + s) * HD + d];
    }
    __syncthreads();
#pragma unroll 1
    for (int p = 0; p < 8; p++) {
        int h2 = p * 2 + (t >> 7);
        int ml = t & 127;
        const float* vr = &vws[h2 * HD];
        float a = 0.f;
#pragma unroll
        for (int d = 0; d < 64; d++) a += cs[ml][d] * vr[d];
        g_z[((size_t)n * 16 + h2) * Sx + m0 + ml] = a;
    }
}

// ---------------- top-128 threshold per row ----------------------------------
__global__ __launch_bounds__(256) void topk_kernel() {
    int row = blockIdx.x, t = threadIdx.x;
    const float* zr = g_z + (size_t)row * Sx;
    unsigned v[8];
#pragma unroll
    for (int i = 0; i < 8; i++) v[i] = f2ord(zr[t + i * 256]);
    __shared__ int scnt;
    unsigned lo = 0u, hi = 0xFFFFFFFFu;
    while (lo < hi) {
        unsigned mid = lo + ((hi - lo) >> 1);
        int c = 0;
#pragma unroll
        for (int i = 0; i < 8; i++) c += (v[i] > mid);
#pragma unroll
        for (int off = 16; off; off >>= 1) c += __shfl_xor_sync(~0u, c, off);
        __syncthreads();
        if (t == 0) scnt = 0;
        __syncthreads();
        if ((t & 31) == 0) atomicAdd(&scnt, c);
        __syncthreads();
        int tot = scnt;
        if (tot >= TOPK) lo = mid + 1; else hi = mid;
    }
    if (t == 0) g_thr[row] = lo;
}

// ---------------- fused y+WO GEMM via pre-contracted W2 ----------------------
#define ZBK 16

__global__ __launch_bounds__(256, 3) void zw_gemm(float* __restrict__ out) {
    __shared__ float As[ZBK][128 + 4];
    __shared__ float Bs[ZBK][64 + 4];
    const int tid = threadIdx.x;
    const int tx = tid & 15, ty = tid >> 4;
    const int n0 = blockIdx.x * 64, s0 = blockIdx.y * 128, b = blockIdx.z;

    u64 acc2[4][4];
#pragma unroll
    for (int ip = 0; ip < 4; ip++)
#pragma unroll
        for (int j = 0; j < 4; j++) acc2[ip][j] = 0ull;

    const int rB = tid >> 2, cB = (tid & 3) * 4;

    for (int kc = 0; kc < 256 / ZBK; kc++) {
        const int k0 = kc * ZBK;
        __syncthreads();
#pragma unroll
        for (int it = 0; it < 2; it++) {
            int idx = tid + it * 256;
            int r = idx >> 5, c4 = (idx & 31) * 4;
            int krow = b * 256 + k0 + r;
            unsigned th = g_thr[krow];
            float4 v = *(const float4*)(g_z + (size_t)krow * Sx + s0 + c4);
            v.x = (f2ord(v.x) >= th) ? v.x : 0.f;
            v.y = (f2ord(v.y) >= th) ? v.y : 0.f;
            v.z = (f2ord(v.z) >= th) ? v.z : 0.f;
            v.w = (f2ord(v.w) >= th) ? v.w : 0.f;
            *(float4*)&As[r][c4] = v;
        }
        {
            float4 w = *(const float4*)(g_W2 + (size_t)(n0 + rB) * 256 + k0 + cB);
            Bs[cB + 0][rB] = w.x; Bs[cB + 1][rB] = w.y;
            Bs[cB + 2][rB] = w.z; Bs[cB + 3][rB] = w.w;
        }
        __syncthreads();
#pragma unroll
        for (int kk = 0; kk < ZBK; kk++) {
            ulonglong2 q01 = *(const ulonglong2*)&As[kk][ty * 8];
            ulonglong2 q23 = *(const ulonglong2*)&As[kk][ty * 8 + 4];
            float4 b4 = *(const float4*)&Bs[kk][tx * 4];
            u64 bd;
            bd = dup2(b4.x);
            fma2(acc2[0][0], q01.x, bd); fma2(acc2[1][0], q01.y, bd);
            fma2(acc2[2][0], q23.x, bd); fma2(acc2[3][0], q23.y, bd);
            bd = dup2(b4.y);
            fma2(acc2[0][1], q01.x, bd); fma2(acc2[1][1], q01.y, bd);
            fma2(acc2[2][1], q23.x, bd); fma2(acc2[3][1], q23.y, bd);
            bd = dup2(b4.z);
            fma2(acc2[0][2], q01.x, bd); fma2(acc2[1][2], q01.y, bd);
            fma2(acc2[2][2], q23.x, bd); fma2(acc2[3][2], q23.y, bd);
            bd = dup2(b4.w);
            fma2(acc2[0][3], q01.x, bd); fma2(acc2[1][3], q01.y, bd);
            fma2(acc2[2][3], q23.x, bd); fma2(acc2[3][3], q23.y, bd);
        }
    }
#pragma unroll
    for (int ip = 0; ip < 4; ip++) {
        float x0, y0, x1, y1, x2, y2, x3, y3;
        unpk2(acc2[ip][0], x0, y0); unpk2(acc2[ip][1], x1, y1);
        unpk2(acc2[ip][2], x2, y2); unpk2(acc2[ip][3], x3, y3);
        size_t off0 = (size_t)(b * Sx + s0 + ty * 8 + 2 * ip) * Hx + n0 + tx * 4;
        size_t off1 = off0 + Hx;
        *(float4*)(out + off0) = make_float4(x0, x1, x2, x3);
        *(float4*)(out + off1) = make_float4(y0, y1, y2, y3);
    }
}

// ---------------- reduce sparse weight means ---------------------------------
__global__ void prep_kernel(const float* __restrict__ swv,
                            const float* __restrict__ swo) {
    int t = blockIdx.x * 64 + threadIdx.x;
    int h = t >> 6, d = t & 63;
    float s1 = 0.f, s2 = 0.f;
#pragma unroll 4
    for (int k = 0; k < 128; k++) {
        s1 += swv[((size_t)(h * 64 + d)) * 128 + k];
        s2 += swo[((size_t)(h * 128 + k)) * 64 + d];
    }
    g_vw[t] = s1 * (1.f / 128.f);
    g_ow[t] = s2 * (1.f / 128.f);
}

// ---------------- W2[o][h*16+h2] = sum_d ow[h2,d] * WO[o, h*64+d] -----------
__global__ void prep2_kernel(const float* __restrict__ WO) {
    int o = blockIdx.x, t = threadIdx.x;
    int h = t >> 4, h2 = t & 15;
    const float* wo = WO + (size_t)o * Hx + h * 64;
    const float* ow = g_ow + h2 * 64;
    float s = 0.f;
#pragma unroll 8
    for (int d = 0; d < 64; d++) s += ow[d] * wo[d];
    g_W2[(size_t)o * 256 + t] = s;
}

// ---------------- launch ----------------------------------------------------
extern "C" void kernel_launch(void* const* d_in, const int* in_sizes, int n_in,
                              void* d_out, int out_size) {
    const float* x   = (const float*)d_in[0];
    const float* WQ  = (const float*)d_in[1];
    const float* WK  = (const float*)d_in[2];
    const float* WV  = (const float*)d_in[3];
    const float* WO  = (const float*)d_in[4];
    const float* qw  = (const float*)d_in[5];
    const float* qb  = (const float*)d_in[6];
    const float* kw  = (const float*)d_in[7];
    const float* kb  = (const float*)d_in[8];
    const float* swv = (const float*)d_in[9];
    const float* swo = (const float*)d_in[10];
    float* out = (float*)d_out;

    float *pQ, *pK, *pV;
    cudaGetSymbolAddress((void**)&pQ, g_Q);
    cudaGetSymbolAddress((void**)&pK, g_K);
    cudaGetSymbolAddress((void**)&pV, g_V);

    cudaFuncSetAttribute(attn_kernel,
                         cudaFuncAttributeMaxDynamicSharedMemorySize, ATTN_SMEM);

    prep_kernel<<<16, 64>>>(swv, swo);
    prep2_kernel<<<1024, 256>>>(WO);

    sgemm_qkv<<<dim3(Hx / BN, BSx / BM, 3), 256>>>(
        x, WQ, WK, WV, pQ, pK, pV, qw, qb, kw, kb, BSx, Hx, Hx);

    attn_kernel<<<dim3(Sx / QT, NH, Bx), 256, ATTN_SMEM>>>(pQ, pK, pV);

    z_kernel<<<dim3(Sx / 128, 32), 256>>>();
    topk_kernel<<<512, 256>>>();

    zw_gemm<<<dim3(Hx / 64, Sx / 128, Bx), 256>>>(out);
}

// round 15
// speedup vs baseline: 1.2675x; 1.1171x over previous
#include <cuda_runtime.h>
#include <cstdint>
#include <cstddef>

// ---------------- problem constants ----------------
#define Bx 2
#define Sx 2048
#define Hx 1024
#define NH 16
#define HD 64
#define BSx (Bx*Sx)          // 4096
#define TOPK 128
#define LN_EPS 1e-5f

typedef unsigned long long u64;

// ---------------- packed f32x2 helpers ----------------
__device__ __forceinline__ u64 pack2(float x, float y) {
    u64 r; asm("mov.b64 %0,{%1,%2};" : "=l"(r) : "f"(x), "f"(y)); return r;
}
__device__ __forceinline__ u64 dup2(float x) { return pack2(x, x); }
__device__ __forceinline__ void unpk2(u64 v, float& x, float& y) {
    asm("mov.b64 {%0,%1},%2;" : "=f"(x), "=f"(y) : "l"(v));
}
__device__ __forceinline__ void fma2(u64& d, u64 a, u64 b) {
    asm("fma.rn.f32x2 %0,%1,%2,%0;" : "+l"(d) : "l"(a), "l"(b));
}
__device__ __forceinline__ void mul2(u64& d, u64 a) {
    asm("mul.rn.f32x2 %0,%0,%1;" : "+l"(d) : "l"(a));
}
__device__ __forceinline__ void add2(u64& d, u64 a) {
    asm("add.rn.f32x2 %0,%0,%1;" : "+l"(d) : "l"(a));
}
__device__ __forceinline__ void sub2(u64& d, u64 a) {
    asm("sub.rn.f32x2 %0,%0,%1;" : "+l"(d) : "l"(a));
}

// ---------------- scratch (device globals; no allocation) ----------------
__device__ float    g_Q[BSx*Hx];
__device__ float    g_K[BSx*Hx];
__device__ float    g_V[BSx*Hx];
__device__ float    g_Vp[Bx*NH*Sx*16];   // V pre-projected onto vw (16 cols)
__device__ float    g_z[32*16*2048];
__device__ unsigned g_thr[32*16];
__device__ float    g_vw[NH*HD];
__device__ float    g_ow[NH*HD];
__device__ float    g_W2[Hx*256];

__device__ __forceinline__ unsigned f2ord(float f) {
    unsigned u = __float_as_uint(f);
    return (u >> 31) ? ~u : (u | 0x80000000u);
}

// ---------------- SGEMM (NT) row-paired + fused LN epilogue ------------------
#define BM 128
#define BN 64
#define BK 16

__global__ __launch_bounds__(256, 3) void sgemm_qkv(
    const float* __restrict__ A,
    const float* __restrict__ B0, const float* __restrict__ B1,
    const float* __restrict__ B2,
    float* __restrict__ C0, float* __restrict__ C1, float* __restrict__ C2,
    const float* __restrict__ qw, const float* __restrict__ qb,
    const float* __restrict__ kw, const float* __restrict__ kb,
    int M, int N, int K) {
    __shared__ float As[2][BK][BM + 4];
    __shared__ float Bs[2][BK][BN + 4];
    const int tid = threadIdx.x;
    const int tx = tid & 15, ty = tid >> 4;
    const int n0 = blockIdx.x * BN, m0 = blockIdx.y * BM;

    const float* B = (blockIdx.z == 0) ? B0 : (blockIdx.z == 1) ? B1 : B2;
    float*       C = (blockIdx.z == 0) ? C0 : (blockIdx.z == 1) ? C1 : C2;

    u64 acc2[4][4];
#pragma unroll
    for (int ip = 0; ip < 4; ip++)
#pragma unroll
        for (int j = 0; j < 4; j++) acc2[ip][j] = 0ull;

    const int rA = tid >> 2, cA = (tid & 3) * 4;
    const int rB = tid >> 2, cB = (tid & 3) * 4;

    float4 pa0 = *(const float4*)(A + (size_t)(m0 + rA) * K + cA);
    float4 pa1 = *(const float4*)(A + (size_t)(m0 + rA + 64) * K + cA);
    float4 pb  = *(const float4*)(B + (size_t)(n0 + rB) * K + cB);

    const int nk = K / BK;
    for (int t = 0; t < nk; t++) {
        const int buf = t & 1;
        As[buf][cA + 0][rA] = pa0.x; As[buf][cA + 1][rA] = pa0.y;
        As[buf][cA + 2][rA] = pa0.z; As[buf][cA + 3][rA] = pa0.w;
        As[buf][cA + 0][rA + 64] = pa1.x; As[buf][cA + 1][rA + 64] = pa1.y;
        As[buf][cA + 2][rA + 64] = pa1.z; As[buf][cA + 3][rA + 64] = pa1.w;
        Bs[buf][cB + 0][rB] = pb.x; Bs[buf][cB + 1][rB] = pb.y;
        Bs[buf][cB + 2][rB] = pb.z; Bs[buf][cB + 3][rB] = pb.w;
        __syncthreads();
        if (t + 1 < nk) {
            int k0 = (t + 1) * BK;
            pa0 = *(const float4*)(A + (size_t)(m0 + rA) * K + k0 + cA);
            pa1 = *(const float4*)(A + (size_t)(m0 + rA + 64) * K + k0 + cA);
            pb  = *(const float4*)(B + (size_t)(n0 + rB) * K + k0 + cB);
        }
#pragma unroll
        for (int kk = 0; kk < BK; kk++) {
            ulonglong2 q01 = *(const ulonglong2*)&As[buf][kk][ty * 8];
            ulonglong2 q23 = *(const ulonglong2*)&As[buf][kk][ty * 8 + 4];
            float4 b4 = *(const float4*)&Bs[buf][kk][tx * 4];
            u64 bd;
            bd = dup2(b4.x);
            fma2(acc2[0][0], q01.x, bd); fma2(acc2[1][0], q01.y, bd);
            fma2(acc2[2][0], q23.x, bd); fma2(acc2[3][0], q23.y, bd);
            bd = dup2(b4.y);
            fma2(acc2[0][1], q01.x, bd); fma2(acc2[1][1], q01.y, bd);
            fma2(acc2[2][1], q23.x, bd); fma2(acc2[3][1], q23.y, bd);
            bd = dup2(b4.z);
            fma2(acc2[0][2], q01.x, bd); fma2(acc2[1][2], q01.y, bd);
            fma2(acc2[2][2], q23.x, bd); fma2(acc2[3][2], q23.y, bd);
            bd = dup2(b4.w);
            fma2(acc2[0][3], q01.x, bd); fma2(acc2[1][3], q01.y, bd);
            fma2(acc2[2][3], q23.x, bd); fma2(acc2[3][3], q23.y, bd);
        }
    }

    const bool doln = (blockIdx.z < 2);
    float4 wv = {0, 0, 0, 0}, bv = {0, 0, 0, 0};
    if (doln) {
        const float* w  = (blockIdx.z == 0) ? qw : kw;
        const float* bb = (blockIdx.z == 0) ? qb : kb;
        wv = *(const float4*)&w[tx * 4];
        bv = *(const float4*)&bb[tx * 4];
    }
#pragma unroll
    for (int ip = 0; ip < 4; ip++) {
        u64 v0 = acc2[ip][0], v1 = acc2[ip][1], v2 = acc2[ip][2], v3 = acc2[ip][3];
        if (doln) {
            u64 s2 = v0; add2(s2, v1); add2(s2, v2); add2(s2, v3);
#pragma unroll
            for (int off = 8; off; off >>= 1) {
                u64 o = __shfl_xor_sync(~0u, s2, off, 16);
                add2(s2, o);
            }
            u64 mu2 = s2; mul2(mu2, dup2(1.f / 64.f));
            sub2(v0, mu2); sub2(v1, mu2); sub2(v2, mu2); sub2(v3, mu2);
            u64 q2 = 0ull;
            fma2(q2, v0, v0); fma2(q2, v1, v1);
            fma2(q2, v2, v2); fma2(q2, v3, v3);
#pragma unroll
            for (int off = 8; off; off >>= 1) {
                u64 o = __shfl_xor_sync(~0u, q2, off, 16);
                add2(q2, o);
            }
            float qa, qb2;
            unpk2(q2, qa, qb2);
            u64 rs2 = pack2(rsqrtf(qa * (1.f / 64.f) + LN_EPS),
                            rsqrtf(qb2 * (1.f / 64.f) + LN_EPS));
            mul2(v0, rs2); mul2(v1, rs2); mul2(v2, rs2); mul2(v3, rs2);
            u64 t;
            t = dup2(bv.x); fma2(t, v0, dup2(wv.x)); v0 = t;
            t = dup2(bv.y); fma2(t, v1, dup2(wv.y)); v1 = t;
            t = dup2(bv.z); fma2(t, v2, dup2(wv.z)); v2 = t;
            t = dup2(bv.w); fma2(t, v3, dup2(wv.w)); v3 = t;
        }
        float x0, y0, x1, y1, x2, y2, x3, y3;
        unpk2(v0, x0, y0); unpk2(v1, x1, y1);
        unpk2(v2, x2, y2); unpk2(v3, x3, y3);
        size_t off0 = (size_t)(m0 + ty * 8 + 2 * ip) * N + n0 + tx * 4;
        size_t off1 = off0 + N;
        *(float4*)(C + off0) = make_float4(x0, x1, x2, x3);
        *(float4*)(C + off1) = make_float4(y0, y1, y2, y3);
    }
}

// ---------------- Vp = V . vw^T (16 projections per head-row) ----------------
// grid BSx/16, block 256: thread (row = t>>4, h = t&15). 1024 MACs/thread.
__global__ __launch_bounds__(256) void vp_kernel() {
    __shared__ float wT[64][16];   // wT[d][h2] = g_vw[h2*64 + d]
    const int t = threadIdx.x;
    for (int i = t; i < 1024; i += 256) {
        int d = i >> 4, h2 = i & 15;
        wT[d][h2] = g_vw[h2 * 64 + d];
    }
    __syncthreads();
    const int row = t >> 4, h = t & 15;
    const int bs = blockIdx.x * 16 + row;
    const float* vr = g_V + (size_t)bs * Hx + h * 64;

    u64 acc[8];
#pragma unroll
    for (int p = 0; p < 8; p++) acc[p] = 0ull;

#pragma unroll 4
    for (int c4 = 0; c4 < 16; c4++) {
        float4 v = *(const float4*)(vr + c4 * 4);
        float vs[4] = {v.x, v.y, v.z, v.w};
#pragma unroll
        for (int j = 0; j < 4; j++) {
            const int d = c4 * 4 + j;
            u64 vd = dup2(vs[j]);
            ulonglong2 wA = *(const ulonglong2*)&wT[d][0];
            ulonglong2 wB = *(const ulonglong2*)&wT[d][4];
            ulonglong2 wC = *(const ulonglong2*)&wT[d][8];
            ulonglong2 wD = *(const ulonglong2*)&wT[d][12];
            fma2(acc[0], vd, wA.x); fma2(acc[1], vd, wA.y);
            fma2(acc[2], vd, wB.x); fma2(acc[3], vd, wB.y);
            fma2(acc[4], vd, wC.x); fma2(acc[5], vd, wC.y);
            fma2(acc[6], vd, wD.x); fma2(acc[7], vd, wD.y);
        }
    }
    const int b = bs >> 11, s = bs & 2047;
    float* op = g_Vp + ((size_t)(b * NH + h) * Sx + s) * 16;
#pragma unroll
    for (int p = 0; p < 4; p++) {
        float a0, a1, a2, a3;
        unpk2(acc[2 * p],     a0, a1);
        unpk2(acc[2 * p + 1], a2, a3);
        *(float4*)(op + p * 4) = make_float4(a0, a1, a2, a3);
    }
}

// ---------------- flash attention v7: 16-col GEMM2 via Vp, scatter to z ------
// GEMM2 output cols = 16 projections (4x fewer FLOPs). Epilogue writes z
// directly with the reference's mixing map; z_kernel eliminated.
#define QT 128
#define KT 64
#define QS_ST 132
#define KS_ST 68
#define VP_ST 20
#define PS_ST 132
#define OFF_KS (64*QS_ST)
#define OFF_VP (OFF_KS + 64*KS_ST)
#define OFF_PS (OFF_VP + KT*VP_ST)
#define ATTN_SMEM ((OFF_PS + KT*PS_ST) * 4)   // 90112 B

__global__ __launch_bounds__(256, 2) void attn_kernel(const float* __restrict__ Qg,
                                                      const float* __restrict__ Kg) {
    extern __shared__ float sm[];
    float* Qs  = sm;               // [k=64][m=128+4]
    float* Ks  = sm + OFF_KS;      // [k=64][j=64+4]
    float* Vps = sm + OFF_VP;      // [c=64][h2=16+4]
    float* Ps  = sm + OFF_PS;      // [c=64][m=128+4]

    const int qt = blockIdx.x, h = blockIdx.y, b = blockIdx.z;
    const int tid = threadIdx.x;
    const int tx = tid & 15, ty = tid >> 4;
    const int q0 = qt * QT;
    const float scale = 0.125f;

    const float* qp = Qg + (size_t)(b * Sx + q0) * Hx + h * HD;
#pragma unroll
    for (int it = 0; it < 8; it++) {
        int idx = tid + it * 256;
        int r = idx >> 4, c4 = (idx & 15) * 4;
        float4 v = *(const float4*)(qp + (size_t)r * Hx + c4);
        Qs[(c4 + 0) * QS_ST + r] = v.x * scale;
        Qs[(c4 + 1) * QS_ST + r] = v.y * scale;
        Qs[(c4 + 2) * QS_ST + r] = v.z * scale;
        Qs[(c4 + 3) * QS_ST + r] = v.w * scale;
    }

    u64 acc2[4];    // [row-pair ip], single col h2 = tx
    u64 l2[4];
#pragma unroll
    for (int ip = 0; ip < 4; ip++) { acc2[ip] = 0ull; l2[ip] = 0ull; }

    const float* vpbase = g_Vp + (size_t)(b * NH + h) * Sx * 16;

    for (int kt = 0; kt < Sx / KT; kt++) {
        __syncthreads();
        const float* kp = Kg + (size_t)(b * Sx + kt * KT) * Hx + h * HD;
#pragma unroll
        for (int it = 0; it < 4; it++) {
            int idx = tid + it * 256;
            int r = idx >> 4, c4 = (idx & 15) * 4;
            float4 kv = *(const float4*)(kp + (size_t)r * Hx + c4);
            Ks[(c4 + 0) * KS_ST + r] = kv.x;
            Ks[(c4 + 1) * KS_ST + r] = kv.y;
            Ks[(c4 + 2) * KS_ST + r] = kv.z;
            Ks[(c4 + 3) * KS_ST + r] = kv.w;
        }
        {   // Vp tile: 64 rows x 16 cols = 256 float4 chunks, 1 per thread
            int r = tid >> 2, c4 = (tid & 3) * 4;
            float4 vv = *(const float4*)(vpbase + (size_t)(kt * KT + r) * 16 + c4);
            *(float4*)&Vps[r * VP_ST + c4] = vv;
        }
        __syncthreads();

        // GEMM1: 8 rows (4 f32x2 pairs) x 4 score cols per thread (unchanged)
        u64 s2[4][4];
#pragma unroll
        for (int ip = 0; ip < 4; ip++)
#pragma unroll
            for (int j = 0; j < 4; j++) s2[ip][j] = 0ull;
#pragma unroll 16
        for (int kk = 0; kk < 64; kk++) {
            ulonglong2 q01 = *(const ulonglong2*)&Qs[kk * QS_ST + ty * 8];
            ulonglong2 q23 = *(const ulonglong2*)&Qs[kk * QS_ST + ty * 8 + 4];
            float4 k4 = *(const float4*)&Ks[kk * KS_ST + tx * 4];
            u64 kd;
            kd = dup2(k4.x);
            fma2(s2[0][0], q01.x, kd); fma2(s2[1][0], q01.y, kd);
            fma2(s2[2][0], q23.x, kd); fma2(s2[3][0], q23.y, kd);
            kd = dup2(k4.y);
            fma2(s2[0][1], q01.x, kd); fma2(s2[1][1], q01.y, kd);
            fma2(s2[2][1], q23.x, kd); fma2(s2[3][1], q23.y, kd);
            kd = dup2(k4.z);
            fma2(s2[0][2], q01.x, kd); fma2(s2[1][2], q01.y, kd);
            fma2(s2[2][2], q23.x, kd); fma2(s2[3][2], q23.y, kd);
            kd = dup2(k4.w);
            fma2(s2[0][3], q01.x, kd); fma2(s2[1][3], q01.y, kd);
            fma2(s2[2][3], q23.x, kd); fma2(s2[3][3], q23.y, kd);
        }

        // p = exp(s); accumulate l; row-pair stores into Ps[c][m]
#pragma unroll
        for (int ip = 0; ip < 4; ip++) {
#pragma unroll
            for (int j = 0; j < 4; j++) {
                float f0, f1;
                unpk2(s2[ip][j], f0, f1);
                u64 pr = pack2(__expf(f0), __expf(f1));
                add2(l2[ip], pr);
                *(u64*)&Ps[(tx * 4 + j) * PS_ST + ty * 8 + 2 * ip] = pr;
            }
        }
        __syncthreads();

        // GEMM2 (16 cols): acc2[ip] += P(row-pair, c) * Vp[c][tx]
#pragma unroll 8
        for (int c = 0; c < KT; c++) {
            ulonglong2 pA = *(const ulonglong2*)&Ps[c * PS_ST + ty * 8];
            ulonglong2 pB = *(const ulonglong2*)&Ps[c * PS_ST + ty * 8 + 4];
            u64 vd = dup2(Vps[c * VP_ST + tx]);
            fma2(acc2[0], pA.x, vd); fma2(acc2[1], pA.y, vd);
            fma2(acc2[2], pB.x, vd); fma2(acc2[3], pB.y, vd);
        }
    }

    // paired row-sum reduction across the 16-lane tx group
#pragma unroll
    for (int ip = 0; ip < 4; ip++) {
#pragma unroll
        for (int off = 8; off; off >>= 1) {
            u64 o = __shfl_xor_sync(~0u, l2[ip], off, 16);
            add2(l2[ip], o);
        }
    }

    // scatter z values: row = (b*16 + t2>>11)*16 + h2(tx), col = t2 & 2047,
    // with t2 = s_q*16 + h  (reference mixing map)
#pragma unroll
    for (int ip = 0; ip < 4; ip++) {
        float la, lb;
        unpk2(l2[ip], la, lb);
        float xa, xb;
        unpk2(acc2[ip], xa, xb);
        int sq = q0 + ty * 8 + 2 * ip;
        int t2a = sq * 16 + h;
        int t2b = t2a + 16;
        g_z[((size_t)((b * 16 + (t2a >> 11)) * 16 + tx)) * Sx + (t2a & 2047)] =
            xa * (1.f / la);
        g_z[((size_t)((b * 16 + (t2b >> 11)) * 16 + tx)) * Sx + (t2b & 2047)] =
            xb * (1.f / lb);
    }
}

// ---------------- top-128 threshold per row ----------------------------------
__global__ __launch_bounds__(256) void topk_kernel() {
    int row = blockIdx.x, t = threadIdx.x;
    const float* zr = g_z + (size_t)row * Sx;
    unsigned v[8];
#pragma unroll
    for (int i = 0; i < 8; i++) v[i] = f2ord(zr[t + i * 256]);
    __shared__ int scnt;
    unsigned lo = 0u, hi = 0xFFFFFFFFu;
    while (lo < hi) {
        unsigned mid = lo + ((hi - lo) >> 1);
        int c = 0;
#pragma unroll
        for (int i = 0; i < 8; i++) c += (v[i] > mid);
#pragma unroll
        for (int off = 16; off; off >>= 1) c += __shfl_xor_sync(~0u, c, off);
        __syncthreads();
        if (t == 0) scnt = 0;
        __syncthreads();
        if ((t & 31) == 0) atomicAdd(&scnt, c);
        __syncthreads();
        int tot = scnt;
        if (tot >= TOPK) lo = mid + 1; else hi = mid;
    }
    if (t == 0) g_thr[row] = lo;
}

// ---------------- fused y+WO GEMM via pre-contracted W2 ----------------------
#define ZBK 16

__global__ __launch_bounds__(256, 3) void zw_gemm(float* __restrict__ out) {
    __shared__ float As[ZBK][128 + 4];
    __shared__ float Bs[ZBK][64 + 4];
    const int tid = threadIdx.x;
    const int tx = tid & 15, ty = tid >> 4;
    const int n0 = blockIdx.x * 64, s0 = blockIdx.y * 128, b = blockIdx.z;

    u64 acc2[4][4];
#pragma unroll
    for (int ip = 0; ip < 4; ip++)
#pragma unroll
        for (int j = 0; j < 4; j++) acc2[ip][j] = 0ull;

    const int rB = tid >> 2, cB = (tid & 3) * 4;

    for (int kc = 0; kc < 256 / ZBK; kc++) {
        const int k0 = kc * ZBK;
        __syncthreads();
#pragma unroll
        for (int it = 0; it < 2; it++) {
            int idx = tid + it * 256;
            int r = idx >> 5, c4 = (idx & 31) * 4;
            int krow = b * 256 + k0 + r;
            unsigned th = g_thr[krow];
            float4 v = *(const float4*)(g_z + (size_t)krow * Sx + s0 + c4);
            v.x = (f2ord(v.x) >= th) ? v.x : 0.f;
            v.y = (f2ord(v.y) >= th) ? v.y : 0.f;
            v.z = (f2ord(v.z) >= th) ? v.z : 0.f;
            v.w = (f2ord(v.w) >= th) ? v.w : 0.f;
            *(float4*)&As[r][c4] = v;
        }
        {
            float4 w = *(const float4*)(g_W2 + (size_t)(n0 + rB) * 256 + k0 + cB);
            Bs[cB + 0][rB] = w.x; Bs[cB + 1][rB] = w.y;
            Bs[cB + 2][rB] = w.z; Bs[cB + 3][rB] = w.w;
        }
        __syncthreads();
#pragma unroll
        for (int kk = 0; kk < ZBK; kk++) {
            ulonglong2 q01 = *(const ulonglong2*)&As[kk][ty * 8];
            ulonglong2 q23 = *(const ulonglong2*)&As[kk][ty * 8 + 4];
            float4 b4 = *(const float4*)&Bs[kk][tx * 4];
            u64 bd;
            bd = dup2(b4.x);
            fma2(acc2[0][0], q01.x, bd); fma2(acc2[1][0], q01.y, bd);
            fma2(acc2[2][0], q23.x, bd); fma2(acc2[3][0], q23.y, bd);
            bd = dup2(b4.y);
            fma2(acc2[0][1], q01.x, bd); fma2(acc2[1][1], q01.y, bd);
            fma2(acc2[2][1], q23.x, bd); fma2(acc2[3][1], q23.y, bd);
            bd = dup2(b4.z);
            fma2(acc2[0][2], q01.x, bd); fma2(acc2[1][2], q01.y, bd);
            fma2(acc2[2][2], q23.x, bd); fma2(acc2[3][2], q23.y, bd);
            bd = dup2(b4.w);
            fma2(acc2[0][3], q01.x, bd); fma2(acc2[1][3], q01.y, bd);
            fma2(acc2[2][3], q23.x, bd); fma2(acc2[3][3], q23.y, bd);
        }
    }
#pragma unroll
    for (int ip = 0; ip < 4; ip++) {
        float x0, y0, x1, y1, x2, y2, x3, y3;
        unpk2(acc2[ip][0], x0, y0); unpk2(acc2[ip][1], x1, y1);
        unpk2(acc2[ip][2], x2, y2); unpk2(acc2[ip][3], x3, y3);
        size_t off0 = (size_t)(b * Sx + s0 + ty * 8 + 2 * ip) * Hx + n0 + tx * 4;
        size_t off1 = off0 + Hx;
        *(float4*)(out + off0) = make_float4(x0, x1, x2, x3);
        *(float4*)(out + off1) = make_float4(y0, y1, y2, y3);
    }
}

// ---------------- reduce sparse weight means ---------------------------------
__global__ void prep_kernel(const float* __restrict__ swv,
                            const float* __restrict__ swo) {
    int t = blockIdx.x * 64 + threadIdx.x;
    int h = t >> 6, d = t & 63;
    float s1 = 0.f, s2 = 0.f;
#pragma unroll 4
    for (int k = 0; k < 128; k++) {
        s1 += swv[((size_t)(h * 64 + d)) * 128 + k];
        s2 += swo[((size_t)(h * 128 + k)) * 64 + d];
    }
    g_vw[t] = s1 * (1.f / 128.f);
    g_ow[t] = s2 * (1.f / 128.f);
}

// ---------------- W2[o][h*16+h2] = sum_d ow[h2,d] * WO[o, h*64+d] -----------
__global__ void prep2_kernel(const float* __restrict__ WO) {
    int o = blockIdx.x, t = threadIdx.x;
    int h = t >> 4, h2 = t & 15;
    const float* wo = WO + (size_t)o * Hx + h * 64;
    const float* ow = g_ow + h2 * 64;
    float s = 0.f;
#pragma unroll 8
    for (int d = 0; d < 64; d++) s += ow[d] * wo[d];
    g_W2[(size_t)o * 256 + t] = s;
}

// ---------------- launch ----------------------------------------------------
extern "C" void kernel_launch(void* const* d_in, const int* in_sizes, int n_in,
                              void* d_out, int out_size) {
    const float* x   = (const float*)d_in[0];
    const float* WQ  = (const float*)d_in[1];
    const float* WK  = (const float*)d_in[2];
    const float* WV  = (const float*)d_in[3];
    const float* WO  = (const float*)d_in[4];
    const float* qw  = (const float*)d_in[5];
    const float* qb  = (const float*)d_in[6];
    const float* kw  = (const float*)d_in[7];
    const float* kb  = (const float*)d_in[8];
    const float* swv = (const float*)d_in[9];
    const float* swo = (const float*)d_in[10];
    float* out = (float*)d_out;

    float *pQ, *pK, *pV;
    cudaGetSymbolAddress((void**)&pQ, g_Q);
    cudaGetSymbolAddress((void**)&pK, g_K);
    cudaGetSymbolAddress((void**)&pV, g_V);

    cudaFuncSetAttribute(attn_kernel,
                         cudaFuncAttributeMaxDynamicSharedMemorySize, ATTN_SMEM);

    prep_kernel<<<16, 64>>>(swv, swo);
    prep2_kernel<<<1024, 256>>>(WO);

    sgemm_qkv<<<dim3(Hx / BN, BSx / BM, 3), 256>>>(
        x, WQ, WK, WV, pQ, pK, pV, qw, qb, kw, kb, BSx, Hx, Hx);

    vp_kernel<<<BSx / 16, 256>>>();

    attn_kernel<<<dim3(Sx / QT, NH, Bx), 256, ATTN_SMEM>>>(pQ, pK);

    topk_kernel<<<512, 256>>>();

    zw_gemm<<<dim3(Hx / 64, Sx / 128, Bx), 256>>>(out);
}